// round 15
// baseline (speedup 1.0000x reference)
#include <cuda_runtime.h>
#include <cuda_bf16.h>
#include <cstdint>
#include <cstddef>

static constexpr int    N_  = 3072;
static constexpr int    C_  = 256;
static constexpr int    H_  = 4;
static constexpr int    D_  = 64;
static constexpr size_t HS_ = (size_t)N_ * N_;
static constexpr size_t QS_ = (size_t)N_ * D_;

typedef __nv_bfloat16 bf;

// ---------------- device scratch ----------------
__device__ bf g_featC_h[N_ * C_],      g_featC_l[N_ * C_];
__device__ bf g_featR_h[N_ * D_],      g_featR_l[N_ * D_];
__device__ bf g_projW_h[C_ * D_],      g_projW_l[C_ * D_];
__device__ bf g_qkvcW_h[3 * C_ * C_],  g_qkvcW_l[3 * C_ * C_];
__device__ bf g_qkvrW_h[3 * C_ * C_],  g_qkvrW_l[3 * C_ * C_];
__device__ bf g_l1cW_h[4 * C_ * C_],   g_l1cW_l[4 * C_ * C_];
__device__ bf g_l1rW_h[4 * C_ * C_],   g_l1rW_l[4 * C_ * C_];
__device__ bf g_l2cW_h[16 * C_ * C_],  g_l2cW_l[16 * C_ * C_];
__device__ bf g_l2rW_h[16 * C_ * C_],  g_l2rW_l[16 * C_ * C_];
__device__ bf g_regp_h[N_ * C_],       g_regp_l[N_ * C_];
__device__ bf g_qnc_h[H_ * N_ * D_],   g_qnc_l[H_ * N_ * D_];
__device__ bf g_knc_h[H_ * N_ * D_],   g_knc_l[H_ * N_ * D_];
__device__ bf g_qnr_h[H_ * N_ * D_],   g_qnr_l[H_ * N_ * D_];
__device__ bf g_knr_h[H_ * N_ * D_],   g_knr_l[H_ * N_ * D_];
__device__ bf g_vnfc_h[N_ * C_];
__device__ bf g_vnfr_h[N_ * C_];
__device__ bf g_attn_h[(size_t)H_ * N_ * N_];
__device__ bf g_attn_l[(size_t)H_ * N_ * N_];
__device__ bf g_enhc_h[N_ * 2 * C_],   g_enhc_l[N_ * 2 * C_];
__device__ bf g_enhr_h[N_ * 2 * C_],   g_enhr_l[N_ * 2 * C_];
__device__ bf g_poolc_h[N_ * 4 * C_],  g_poolc_l[N_ * 4 * C_];
__device__ bf g_poolr_h[N_ * 4 * C_],  g_poolr_l[N_ * 4 * C_];
__device__ float g_qkv_cls[N_ * 3 * C_];
__device__ float g_qkv_reg[N_ * 3 * C_];
__device__ float g_vfused [H_ * N_ * 2 * D_];   // per head [k, 128] = [v_cls | v_reg]
__device__ float g_av     [H_ * N_ * 2 * D_];
__device__ float g_bufA[(size_t)H_ * N_ * N_];
__device__ float g_bufB[(size_t)H_ * N_ * N_];
__device__ float g_sr2v[(size_t)N_ * N_];
__device__ int   g_sr2i[(size_t)N_ * N_];
__device__ int   g_sr2c[N_];
__device__ float g_objv[(size_t)N_ * N_];
__device__ int   g_obji[(size_t)N_ * N_];
__device__ int   g_objc[N_];

// ---------------- primitives ----------------
__device__ __forceinline__ uint32_t cvta_shared(const void* p) {
    return (uint32_t)__cvta_generic_to_shared(p);
}
__device__ __forceinline__ void ldmatrix_x4(uint32_t& r0, uint32_t& r1,
                                            uint32_t& r2, uint32_t& r3, uint32_t addr) {
    asm volatile("ldmatrix.sync.aligned.m8n8.x4.shared.b16 {%0,%1,%2,%3}, [%4];"
                 : "=r"(r0), "=r"(r1), "=r"(r2), "=r"(r3) : "r"(addr));
}
__device__ __forceinline__ void mma_bf16(float* c, uint32_t a0, uint32_t a1,
                                         uint32_t a2, uint32_t a3,
                                         uint32_t b0, uint32_t b1) {
    asm volatile(
        "mma.sync.aligned.m16n8k16.row.col.f32.bf16.bf16.f32 "
        "{%0,%1,%2,%3}, {%4,%5,%6,%7}, {%8,%9}, {%0,%1,%2,%3};"
        : "+f"(c[0]), "+f"(c[1]), "+f"(c[2]), "+f"(c[3])
        : "r"(a0), "r"(a1), "r"(a2), "r"(a3), "r"(b0), "r"(b1));
}
__device__ __forceinline__ void split_bf16(float x, bf& h, bf& l) {
    h = __float2bfloat16_rn(x);
    l = __float2bfloat16_rn(x - __bfloat162float(h));
}

// =======================================================================================
// R12-core GEMM (double-buffered ld/st staging, BK=32, tile 128x128, validated fragment
// mapping) operating on pre-split hi/lo bf16 planes.
//   C[M,N] = alpha * A[M,K] x op(B) (+ bias[col])
//   TRANSB = true : B given as hi/lo planes [N,K] row-major.
//   TRANSB = false: B given as f32 [K,N] row-major (split inline, R12-verbatim path).
//   PASSES = 3: emulated-fp32 (AhBh + AhBl + AlBh).  PASSES = 1: hi only.
//   EPI    = 0: f32 C.  EPI = 1: hi/lo plane C.
// REQUIRES M%128==0, N%128==0, K%32==0.
// =======================================================================================
template <bool TRANSB, int PASSES, int EPI>
__global__ __launch_bounds__(256, 1)
void gemm_tc(int K,
             const bf* __restrict__ Ah, const bf* __restrict__ Al, int lda, size_t sA,
             const bf* __restrict__ Bh, const bf* __restrict__ Bl,
             const float* __restrict__ Bf, int ldb, size_t sB,
             float* __restrict__ Cf, bf* __restrict__ Ch, bf* __restrict__ Cl,
             int ldc, size_t sC,
             float alpha, const float* __restrict__ bias)
{
    constexpr int BM = 128, BN = 128, LDS = 24;
    constexpr int MI = 4, NI = 4;
    constexpr int TSZ = BM * LDS;
    constexpr uint32_t SUB_B = TSZ * 2;
    constexpr uint32_t BUF_B = 2 * SUB_B;

    extern __shared__ bf sm[];
    bf* AsH = sm;
    bf* AsL = sm + 4 * TSZ;
    bf* BsH = sm + 8 * TSZ;
    bf* BsL = sm + 12 * TSZ;

    const int bz = blockIdx.z;
    Ah += bz * sA;
    if (PASSES == 3) Al += bz * sA;
    if (TRANSB) {
        Bh += bz * sB;
        if (PASSES == 3) Bl += bz * sB;
    } else {
        Bf += bz * sB;
    }
    // FIX (R13/R14 bug): batch offset on C was missing — heads clobbered each other.
    if (EPI == 0) {
        Cf += bz * sC;
    } else {
        Ch += bz * sC;
        Cl += bz * sC;
    }

    const int m0   = blockIdx.y * BM;
    const int n0   = blockIdx.x * BN;
    const int tid  = threadIdx.x;
    const int lane = tid & 31;
    const int wid  = tid >> 5;
    const int warpN = wid & 3;
    const int warpM = wid >> 2;

    // ---- A staging coords (R12-identical smem targets) ----
    int am[4], asub[4], akin[4], agk[4];
#pragma unroll
    for (int i = 0; i < 4; i++) {
        int id = tid + i * 256;
        am[i]   = id >> 3;
        int q   = id & 7;
        asub[i] = q >> 2;
        akin[i] = (q & 3) << 2;
        agk[i]  = q << 2;
    }
    // ---- B staging coords ----
    int bn[4], bsub[4], bkin[4], bgk[4];
#pragma unroll
    for (int i = 0; i < 4; i++) {
        int id = tid + i * 256;
        if (TRANSB) {
            bn[i]   = id >> 3;
            int q   = id & 7;
            bsub[i] = q >> 2;
            bkin[i] = (q & 3) << 2;
            bgk[i]  = q << 2;
        } else {
            int k   = id >> 5;
            bn[i]   = (id & 31) << 2;
            bsub[i] = k >> 4;
            bkin[i] = k & 15;
            bgk[i]  = k;
        }
    }

    // ---- ldmatrix per-lane addresses (R12-verbatim) ----
    const int aRow = lane & 15, aChunk = lane >> 4;
    const int bRow = ((lane >> 4) << 3) + (lane & 7), bChunk = (lane >> 3) & 1;
    uint32_t adrAH[MI], adrAL[MI], adrBH[2], adrBL[2];
#pragma unroll
    for (int mi = 0; mi < MI; mi++) {
        int row = warpM * 64 + mi * 16 + aRow;
        adrAH[mi] = cvta_shared(AsH) + row * 48 + aChunk * 16;
        adrAL[mi] = cvta_shared(AsL) + row * 48 + aChunk * 16;
    }
#pragma unroll
    for (int p = 0; p < 2; p++) {
        int row = warpN * 32 + p * 16 + bRow;
        adrBH[p] = cvta_shared(BsH) + row * 48 + bChunk * 16;
        adrBL[p] = cvta_shared(BsL) + row * 48 + bChunk * 16;
    }

    float acc[MI][NI][4];
#pragma unroll
    for (int mi = 0; mi < MI; mi++)
#pragma unroll
        for (int ni = 0; ni < NI; ni++)
#pragma unroll
            for (int j = 0; j < 4; j++) acc[mi][ni][j] = 0.f;

    uint2 ahr[4], alr[4], bhr[4], blr[4];
    float4 bfr[4];
    auto ldg = [&](int k0) {
#pragma unroll
        for (int i = 0; i < 4; i++) {
            ahr[i] = *reinterpret_cast<const uint2*>(Ah + (size_t)(m0 + am[i]) * lda + k0 + agk[i]);
            if (PASSES == 3)
                alr[i] = *reinterpret_cast<const uint2*>(Al + (size_t)(m0 + am[i]) * lda + k0 + agk[i]);
        }
        if (TRANSB) {
#pragma unroll
            for (int i = 0; i < 4; i++) {
                bhr[i] = *reinterpret_cast<const uint2*>(Bh + (size_t)(n0 + bn[i]) * ldb + k0 + bgk[i]);
                if (PASSES == 3)
                    blr[i] = *reinterpret_cast<const uint2*>(Bl + (size_t)(n0 + bn[i]) * ldb + k0 + bgk[i]);
            }
        } else {
#pragma unroll
            for (int i = 0; i < 4; i++)
                bfr[i] = *reinterpret_cast<const float4*>(Bf + (size_t)(k0 + bgk[i]) * ldb + n0 + bn[i]);
        }
    };
    auto sts = [&](int buf) {
#pragma unroll
        for (int i = 0; i < 4; i++) {
            int o = ((buf * 2 + asub[i]) * BM + am[i]) * LDS + akin[i];
            *reinterpret_cast<uint2*>(&AsH[o]) = ahr[i];
            if (PASSES == 3) *reinterpret_cast<uint2*>(&AsL[o]) = alr[i];
        }
        if (TRANSB) {
#pragma unroll
            for (int i = 0; i < 4; i++) {
                int o = ((buf * 2 + bsub[i]) * BN + bn[i]) * LDS + bkin[i];
                *reinterpret_cast<uint2*>(&BsH[o]) = bhr[i];
                if (PASSES == 3) *reinterpret_cast<uint2*>(&BsL[o]) = blr[i];
            }
        } else {
#pragma unroll
            for (int i = 0; i < 4; i++) {
                bf h0, h1, h2, h3, l0, l1, l2, l3;
                split_bf16(bfr[i].x, h0, l0); split_bf16(bfr[i].y, h1, l1);
                split_bf16(bfr[i].z, h2, l2); split_bf16(bfr[i].w, h3, l3);
                int ob = (buf * 2 + bsub[i]) * BN;
                BsH[(ob + bn[i] + 0) * LDS + bkin[i]] = h0;
                BsH[(ob + bn[i] + 1) * LDS + bkin[i]] = h1;
                BsH[(ob + bn[i] + 2) * LDS + bkin[i]] = h2;
                BsH[(ob + bn[i] + 3) * LDS + bkin[i]] = h3;
                if (PASSES == 3) {
                    BsL[(ob + bn[i] + 0) * LDS + bkin[i]] = l0;
                    BsL[(ob + bn[i] + 1) * LDS + bkin[i]] = l1;
                    BsL[(ob + bn[i] + 2) * LDS + bkin[i]] = l2;
                    BsL[(ob + bn[i] + 3) * LDS + bkin[i]] = l3;
                }
            }
        }
    };

    ldg(0);
    sts(0);
    __syncthreads();

    const int S = K >> 5;
    int buf = 0;
    for (int s = 0; s < S; s++) {
        const bool has_next = (s + 1) < S;
        if (has_next) ldg((s + 1) << 5);

#pragma unroll
        for (int sub = 0; sub < 2; sub++) {
            const uint32_t off = (uint32_t)buf * BUF_B + (uint32_t)sub * SUB_B;
            uint32_t aH[MI][4], aL[MI][4], bH[NI][2], bL[NI][2];
#pragma unroll
            for (int mi = 0; mi < MI; mi++) {
                ldmatrix_x4(aH[mi][0], aH[mi][1], aH[mi][2], aH[mi][3], adrAH[mi] + off);
                if (PASSES == 3)
                    ldmatrix_x4(aL[mi][0], aL[mi][1], aL[mi][2], aL[mi][3], adrAL[mi] + off);
            }
#pragma unroll
            for (int p = 0; p < 2; p++) {
                uint32_t r0, r1, r2, r3;
                ldmatrix_x4(r0, r1, r2, r3, adrBH[p] + off);
                bH[2 * p][0] = r0; bH[2 * p][1] = r1;
                bH[2 * p + 1][0] = r2; bH[2 * p + 1][1] = r3;
                if (PASSES == 3) {
                    ldmatrix_x4(r0, r1, r2, r3, adrBL[p] + off);
                    bL[2 * p][0] = r0; bL[2 * p][1] = r1;
                    bL[2 * p + 1][0] = r2; bL[2 * p + 1][1] = r3;
                }
            }
#pragma unroll
            for (int mi = 0; mi < MI; mi++)
#pragma unroll
                for (int ni = 0; ni < NI; ni++) {
                    mma_bf16(acc[mi][ni], aH[mi][0], aH[mi][1], aH[mi][2], aH[mi][3],
                             bH[ni][0], bH[ni][1]);
                    if (PASSES == 3) {
                        mma_bf16(acc[mi][ni], aH[mi][0], aH[mi][1], aH[mi][2], aH[mi][3],
                                 bL[ni][0], bL[ni][1]);
                        mma_bf16(acc[mi][ni], aL[mi][0], aL[mi][1], aL[mi][2], aL[mi][3],
                                 bH[ni][0], bH[ni][1]);
                    }
                }
        }

        if (has_next) {
            sts(buf ^ 1);
            __syncthreads();
            buf ^= 1;
        }
    }

    // ---- epilogue (validated m16n8 D layout) ----
    const int g = lane >> 2, t = lane & 3;
#pragma unroll
    for (int mi = 0; mi < MI; mi++) {
#pragma unroll
        for (int ni = 0; ni < NI; ni++) {
            int col = n0 + warpN * 32 + ni * 8 + t * 2;
            int r0  = m0 + warpM * 64 + mi * 16 + g;
            float2 o0, o1;
            o0.x = alpha * acc[mi][ni][0];
            o0.y = alpha * acc[mi][ni][1];
            o1.x = alpha * acc[mi][ni][2];
            o1.y = alpha * acc[mi][ni][3];
            if (bias) {
                float2 bv = *reinterpret_cast<const float2*>(bias + col);
                o0.x += bv.x; o0.y += bv.y;
                o1.x += bv.x; o1.y += bv.y;
            }
            if (EPI == 0) {
                *reinterpret_cast<float2*>(Cf + (size_t)r0 * ldc + col)       = o0;
                *reinterpret_cast<float2*>(Cf + (size_t)(r0 + 8) * ldc + col) = o1;
            } else {
                bf h0, l0, h1, l1;
                split_bf16(o0.x, h0, l0); split_bf16(o0.y, h1, l1);
                *reinterpret_cast<__nv_bfloat162*>(Ch + (size_t)r0 * ldc + col) = __nv_bfloat162(h0, h1);
                *reinterpret_cast<__nv_bfloat162*>(Cl + (size_t)r0 * ldc + col) = __nv_bfloat162(l0, l1);
                split_bf16(o1.x, h0, l0); split_bf16(o1.y, h1, l1);
                *reinterpret_cast<__nv_bfloat162*>(Ch + (size_t)(r0 + 8) * ldc + col) = __nv_bfloat162(h0, h1);
                *reinterpret_cast<__nv_bfloat162*>(Cl + (size_t)(r0 + 8) * ldc + col) = __nv_bfloat162(l0, l1);
            }
        }
    }
}

static constexpr int GEMM_SMEM = 16 * 128 * 24 * 2;   // 98304 bytes

template <bool TRANSB, int PASSES, int EPI>
static void run_g(int M, int N, int K,
                  const bf* Ah, const bf* Al, int lda, size_t sA,
                  const bf* Bh, const bf* Bl, const float* Bf, int ldb, size_t sB,
                  float* Cf, bf* Ch, bf* Cl, int ldc, size_t sC,
                  float alpha, const float* bias, int batch)
{
    dim3 grid(N / 128, M / 128, batch);
    gemm_tc<TRANSB, PASSES, EPI><<<grid, 256, GEMM_SMEM>>>(
        K, Ah, Al, lda, sA, Bh, Bl, Bf, ldb, sB, Cf, Ch, Cl, ldc, sC, alpha, bias);
}

// ---------------- reductions ----------------
__device__ __forceinline__ float warpSum(float v) {
#pragma unroll
    for (int o = 16; o; o >>= 1) v += __shfl_xor_sync(0xffffffffu, v, o);
    return v;
}
__device__ __forceinline__ float warpMax(float v) {
#pragma unroll
    for (int o = 16; o; o >>= 1) v = fmaxf(v, __shfl_xor_sync(0xffffffffu, v, o));
    return v;
}
__device__ __forceinline__ float blockMax(float v, float* red) {
    v = warpMax(v);
    if ((threadIdx.x & 31) == 0) red[threadIdx.x >> 5] = v;
    __syncthreads();
    float r = red[0];
#pragma unroll
    for (int i = 1; i < 8; i++) r = fmaxf(r, red[i]);
    __syncthreads();
    return r;
}
__device__ __forceinline__ float blockSum(float v, float* red) {
    v = warpSum(v);
    if ((threadIdx.x & 31) == 0) red[threadIdx.x >> 5] = v;
    __syncthreads();
    float r = red[0];
#pragma unroll
    for (int i = 1; i < 8; i++) r += red[i];
    __syncthreads();
    return r;
}

// ---------------- elementwise kernels ----------------
__global__ void split_arr_kernel(const float* __restrict__ s,
                                 bf* __restrict__ h, bf* __restrict__ l, int n)
{
    int t = blockIdx.x * 256 + threadIdx.x;
    if (t < n) {
        bf hh, ll;
        split_bf16(s[t], hh, ll);
        h[t] = hh; l[t] = ll;
    }
}

// QKV split: normalize q,k (k scaled by 25*score or 25), emit hi/lo planes; raw v ->
// vfused f32 panel + enh 'ori' half planes; normalized v -> vnf hi plane (1-pass gram).
__global__ void qkv_split_kernel(const float* __restrict__ qkv,
                                 bf* __restrict__ qh, bf* __restrict__ ql,
                                 bf* __restrict__ kh, bf* __restrict__ kl,
                                 float* __restrict__ vf, int coloff,
                                 bf* __restrict__ vnfh,
                                 bf* __restrict__ ehh, bf* __restrict__ ehl,
                                 const float* __restrict__ scores)
{
    int w = (blockIdx.x * blockDim.x + threadIdx.x) >> 5;
    if (w >= N_ * H_) return;
    int lane = threadIdx.x & 31;
    int h = w & 3;
    int n = w >> 2;

    const float* src = qkv + (size_t)n * (3 * C_) + h * D_;
    float q0 = src[lane],            q1 = src[lane + 32];
    float k0 = src[C_ + lane],       k1 = src[C_ + lane + 32];
    float v0 = src[2 * C_ + lane],   v1 = src[2 * C_ + lane + 32];

    float sq = warpSum(q0 * q0 + q1 * q1);
    float sk = warpSum(k0 * k0 + k1 * k1);
    float sv = warpSum(v0 * v0 + v1 * v1);
    float iq = 1.f / fmaxf(sqrtf(sq), 1e-6f);
    float ik = 1.f / fmaxf(sqrtf(sk), 1e-6f);
    float iv = 1.f / fmaxf(sqrtf(sv), 1e-6f);
    float ks = (scores ? 25.f * scores[n] : 25.f) * ik;

    size_t ho = ((size_t)h * N_ + n) * D_;
    bf hh, ll;
    split_bf16(q0 * iq, hh, ll); qh[ho + lane] = hh;      ql[ho + lane] = ll;
    split_bf16(q1 * iq, hh, ll); qh[ho + lane + 32] = hh; ql[ho + lane + 32] = ll;
    split_bf16(k0 * ks, hh, ll); kh[ho + lane] = hh;      kl[ho + lane] = ll;
    split_bf16(k1 * ks, hh, ll); kh[ho + lane + 32] = hh; kl[ho + lane + 32] = ll;

    size_t vo = ((size_t)h * N_ + n) * (2 * D_) + coloff;
    vf[vo + lane] = v0; vf[vo + lane + 32] = v1;

    size_t fo = (size_t)n * C_ + h * D_;
    vnfh[fo + lane]      = __float2bfloat16_rn(v0 * iv);
    vnfh[fo + lane + 32] = __float2bfloat16_rn(v1 * iv);

    size_t eo = (size_t)n * (2 * C_) + C_ + h * D_;
    split_bf16(v0, hh, ll); ehh[eo + lane] = hh;      ehl[eo + lane] = ll;
    split_bf16(v1, hh, ll); ehh[eo + lane + 32] = hh; ehl[eo + lane + 32] = ll;
}

// fused dual softmax + average (logits pre-scaled); writes attn hi/lo planes.
__global__ void softmax_avg_kernel(const float* __restrict__ lc_all,
                                   const float* __restrict__ lr_all,
                                   bf* __restrict__ ah, bf* __restrict__ al)
{
    __shared__ float sc[N_];
    __shared__ float sr[N_];
    __shared__ float red[8];
    size_t base = (size_t)blockIdx.x * N_;
    const float* lc = lc_all + base;
    const float* lr = lr_all + base;

    float mc = -3.4e38f, mr = -3.4e38f;
    for (int m = threadIdx.x; m < N_; m += 256) {
        float xc = lc[m], xr = lr[m];
        sc[m] = xc; sr[m] = xr;
        mc = fmaxf(mc, xc); mr = fmaxf(mr, xr);
    }
    mc = blockMax(mc, red);
    mr = blockMax(mr, red);

    float tc = 0.f, tr = 0.f;
    for (int m = threadIdx.x; m < N_; m += 256) {
        float ec = expf(sc[m] - mc);
        float er = expf(sr[m] - mr);
        sc[m] = ec; sr[m] = er;
        tc += ec; tr += er;
    }
    tc = blockSum(tc, red);
    tr = blockSum(tr, red);

    float ic = 0.5f / tc, ir = 0.5f / tr;
    for (int m = threadIdx.x; m < N_; m += 256) {
        bf hh, ll;
        split_bf16(sc[m] * ic + sr[m] * ir, hh, ll);
        ah[base + m] = hh; al[base + m] = ll;
    }
}

// sim_round2 + obj_mask -> sparse CSR (deterministic compaction)
__global__ void sim_kernel(const bf* __restrict__ ah, const bf* __restrict__ al,
                           const float* __restrict__ gcls,
                           const float* __restrict__ greg,
                           int*  __restrict__ s_idx, float* __restrict__ s_val,
                           int*  __restrict__ s_cnt,
                           int*  __restrict__ o_idx, float* __restrict__ o_val,
                           int*  __restrict__ o_cnt)
{
    __shared__ float s[N_];
    __shared__ float red[8];
    __shared__ int wcS[8], wcO[8];
    int n = blockIdx.x;
    int tid = threadIdx.x;
    size_t ro = (size_t)n * N_;

    float mx = -3.4e38f;
    for (int m = tid; m < N_; m += 256) {
        float v = 0.f;
#pragma unroll
        for (int h = 0; h < 4; h++) {
            size_t o = (size_t)h * HS_ + ro + m;
            v += __bfloat162float(ah[o]) + __bfloat162float(al[o]);
        }
        v *= 0.25f;
        s[m] = v;
        mx = fmaxf(mx, v);
    }
    mx = blockMax(mx, red);

    float S = 0.f;
    for (int m = tid; m < N_; m += 256) {
        float e  = expf(s[m] - mx);
        float me = (gcls[ro + m] > 0.75f) ? e : 0.f;
        s[m] = me;
        S += me;
    }
    S = blockSum(S, red);
    float invS = 1.f / S;

    float S2 = 0.f;
    for (int m = tid; m < N_; m += 256) S2 += s[m] * invS;
    S2 = blockSum(S2, red);
    float invS2 = 1.f / S2;

    int baseS = 0, baseO = 0;
    int lane = tid & 31, wid = tid >> 5;
    unsigned lt = (lane == 0) ? 0u : (0xffffffffu >> (32 - lane));
    for (int m0 = 0; m0 < N_; m0 += 256) {
        int m = m0 + tid;
        float me = s[m];
        bool ps = (me > 0.f);
        bool po = ps && (greg[ro + m] > 0.99f);

        unsigned bs = __ballot_sync(0xffffffffu, ps);
        unsigned bo = __ballot_sync(0xffffffffu, po);
        if (lane == 0) { wcS[wid] = __popc(bs); wcO[wid] = __popc(bo); }
        __syncthreads();
        int offS = 0, offO = 0, totS = 0, totO = 0;
#pragma unroll
        for (int w = 0; w < 8; w++) {
            int cs = wcS[w], co = wcO[w];
            if (w < wid) { offS += cs; offO += co; }
            totS += cs; totO += co;
        }
        if (ps) {
            int p = baseS + offS + __popc(bs & lt);
            s_idx[ro + p] = m;
            s_val[ro + p] = me * invS;
        }
        if (po) {
            int p = baseO + offO + __popc(bo & lt);
            o_idx[ro + p] = m;
            o_val[ro + p] = me * invS * invS2;
        }
        baseS += totS; baseO += totO;
        __syncthreads();
    }
    if (tid == 0) { s_cnt[n] = baseS; o_cnt[n] = baseO; }
}

// sparse pooled mix on bf16 hi/lo pool planes (reads cols 512:1024, writes 0:512)
__global__ __launch_bounds__(128)
void pool_kernel(const int* __restrict__ idx, const float* __restrict__ val,
                 const int* __restrict__ cnt,
                 bf* __restrict__ ph, bf* __restrict__ pl)
{
    int n = blockIdx.x;
    int k = cnt[n];
    size_t ro = (size_t)n * N_;
    int c = threadIdx.x * 4;

    float acc[4] = {0.f, 0.f, 0.f, 0.f};
    for (int j = 0; j < k; j++) {
        int   m = idx[ro + j];
        float w = val[ro + j];
        size_t o = (size_t)m * 1024 + 512 + c;
        __nv_bfloat162 h0 = *reinterpret_cast<const __nv_bfloat162*>(ph + o);
        __nv_bfloat162 h1 = *reinterpret_cast<const __nv_bfloat162*>(ph + o + 2);
        __nv_bfloat162 l0 = *reinterpret_cast<const __nv_bfloat162*>(pl + o);
        __nv_bfloat162 l1 = *reinterpret_cast<const __nv_bfloat162*>(pl + o + 2);
        acc[0] += w * (__bfloat162float(h0.x) + __bfloat162float(l0.x));
        acc[1] += w * (__bfloat162float(h0.y) + __bfloat162float(l0.y));
        acc[2] += w * (__bfloat162float(h1.x) + __bfloat162float(l1.x));
        acc[3] += w * (__bfloat162float(h1.y) + __bfloat162float(l1.y));
    }
    size_t o = (size_t)n * 1024 + c;
    bf h0, l0, h1, l1;
    split_bf16(acc[0], h0, l0); split_bf16(acc[1], h1, l1);
    *reinterpret_cast<__nv_bfloat162*>(ph + o)     = __nv_bfloat162(h0, h1);
    *reinterpret_cast<__nv_bfloat162*>(pl + o)     = __nv_bfloat162(l0, l1);
    split_bf16(acc[2], h0, l0); split_bf16(acc[3], h1, l1);
    *reinterpret_cast<__nv_bfloat162*>(ph + o + 2) = __nv_bfloat162(h0, h1);
    *reinterpret_cast<__nv_bfloat162*>(pl + o + 2) = __nv_bfloat162(l0, l1);
}

// scatter av f32 [h][n][128] into enh inter halves (hi/lo planes)
__global__ __launch_bounds__(256)
void scatter_av_kernel(const float* __restrict__ av,
                       bf* __restrict__ ech, bf* __restrict__ ecl,
                       bf* __restrict__ erh, bf* __restrict__ erl)
{
    int t = blockIdx.x * 256 + threadIdx.x;
    int h   = t / (N_ * 32);
    int rem = t - h * (N_ * 32);
    int n   = rem >> 5;
    int q   = rem & 31;
    float4 v = *reinterpret_cast<const float4*>(av + ((size_t)h * N_ + n) * 128 + q * 4);
    bf* dh; bf* dl; int col;
    if (q < 16) { dh = ech; dl = ecl; col = h * 64 + q * 4; }
    else        { dh = erh; dl = erl; col = h * 64 + (q - 16) * 4; }
    size_t o = (size_t)n * 512 + col;
    bf h0, l0, h1, l1;
    split_bf16(v.x, h0, l0); split_bf16(v.y, h1, l1);
    *reinterpret_cast<__nv_bfloat162*>(dh + o)     = __nv_bfloat162(h0, h1);
    *reinterpret_cast<__nv_bfloat162*>(dl + o)     = __nv_bfloat162(l0, l1);
    split_bf16(v.z, h0, l0); split_bf16(v.w, h1, l1);
    *reinterpret_cast<__nv_bfloat162*>(dh + o + 2) = __nv_bfloat162(h0, h1);
    *reinterpret_cast<__nv_bfloat162*>(dl + o + 2) = __nv_bfloat162(l0, l1);
}

static void split_arr(const float* s, bf* h, bf* l, int n)
{
    split_arr_kernel<<<(n + 255) / 256, 256>>>(s, h, l, n);
}
template <typename T>
static T* sym(const void* s) { void* p; cudaGetSymbolAddress(&p, s); return (T*)p; }

extern "C" void kernel_launch(void* const* d_in, const int* in_sizes, int n_in,
                              void* d_out, int out_size)
{
    (void)in_sizes; (void)n_in; (void)out_size;

    cudaFuncSetAttribute(gemm_tc<true, 3, 0>,  cudaFuncAttributeMaxDynamicSharedMemorySize, GEMM_SMEM);
    cudaFuncSetAttribute(gemm_tc<true, 3, 1>,  cudaFuncAttributeMaxDynamicSharedMemorySize, GEMM_SMEM);
    cudaFuncSetAttribute(gemm_tc<true, 1, 0>,  cudaFuncAttributeMaxDynamicSharedMemorySize, GEMM_SMEM);
    cudaFuncSetAttribute(gemm_tc<false, 3, 0>, cudaFuncAttributeMaxDynamicSharedMemorySize, GEMM_SMEM);

    const float* cls_features = (const float*)d_in[0];
    const float* reg_features = (const float*)d_in[1];
    const float* cls_scores   = (const float*)d_in[2];
    const float* reg_proj_w   = (const float*)d_in[3];
    const float* qkv_cls_w    = (const float*)d_in[4];
    const float* qkv_reg_w    = (const float*)d_in[5];
    const float* l1_cls_w     = (const float*)d_in[6];
    const float* l1_cls_b     = (const float*)d_in[7];
    const float* l1_reg_w     = (const float*)d_in[8];
    const float* l1_reg_b     = (const float*)d_in[9];
    const float* l2_cls_w     = (const float*)d_in[10];
    const float* l2_cls_b     = (const float*)d_in[11];
    const float* l2_reg_w     = (const float*)d_in[12];
    const float* l2_reg_b     = (const float*)d_in[13];
    float* out = (float*)d_out;

    bf *fCh = sym<bf>(g_featC_h), *fCl = sym<bf>(g_featC_l);
    bf *fRh = sym<bf>(g_featR_h), *fRl = sym<bf>(g_featR_l);
    bf *pWh = sym<bf>(g_projW_h), *pWl = sym<bf>(g_projW_l);
    bf *qcWh = sym<bf>(g_qkvcW_h), *qcWl = sym<bf>(g_qkvcW_l);
    bf *qrWh = sym<bf>(g_qkvrW_h), *qrWl = sym<bf>(g_qkvrW_l);
    bf *l1cWh = sym<bf>(g_l1cW_h), *l1cWl = sym<bf>(g_l1cW_l);
    bf *l1rWh = sym<bf>(g_l1rW_h), *l1rWl = sym<bf>(g_l1rW_l);
    bf *l2cWh = sym<bf>(g_l2cW_h), *l2cWl = sym<bf>(g_l2cW_l);
    bf *l2rWh = sym<bf>(g_l2rW_h), *l2rWl = sym<bf>(g_l2rW_l);
    bf *rph = sym<bf>(g_regp_h),  *rpl = sym<bf>(g_regp_l);
    bf *qch = sym<bf>(g_qnc_h), *qcl = sym<bf>(g_qnc_l);
    bf *kch = sym<bf>(g_knc_h), *kcl = sym<bf>(g_knc_l);
    bf *qrh = sym<bf>(g_qnr_h), *qrl = sym<bf>(g_qnr_l);
    bf *krh = sym<bf>(g_knr_h), *krl = sym<bf>(g_knr_l);
    bf *vnfc = sym<bf>(g_vnfc_h), *vnfr = sym<bf>(g_vnfr_h);
    bf *ath = sym<bf>(g_attn_h), *atl = sym<bf>(g_attn_l);
    bf *ech = sym<bf>(g_enhc_h), *ecl = sym<bf>(g_enhc_l);
    bf *erh = sym<bf>(g_enhr_h), *erl = sym<bf>(g_enhr_l);
    bf *pch = sym<bf>(g_poolc_h), *pcl = sym<bf>(g_poolc_l);
    bf *prh = sym<bf>(g_poolr_h), *prl = sym<bf>(g_poolr_l);
    float *qkvc = sym<float>(g_qkv_cls), *qkvr = sym<float>(g_qkv_reg);
    float *vf = sym<float>(g_vfused), *av = sym<float>(g_av);
    float *bufA = sym<float>(g_bufA), *bufB = sym<float>(g_bufB);
    float *sr2v = sym<float>(g_sr2v), *objv = sym<float>(g_objv);
    int *sr2i = sym<int>(g_sr2i), *sr2c = sym<int>(g_sr2c);
    int *obji = sym<int>(g_obji), *objc = sym<int>(g_objc);

    // 0) pre-split inputs & weights into hi/lo bf16 planes
    split_arr(cls_features, fCh, fCl, N_ * C_);
    split_arr(reg_features, fRh, fRl, N_ * D_);
    split_arr(reg_proj_w,   pWh, pWl, C_ * D_);
    split_arr(qkv_cls_w,    qcWh, qcWl, 3 * C_ * C_);
    split_arr(qkv_reg_w,    qrWh, qrWl, 3 * C_ * C_);
    split_arr(l1_cls_w,     l1cWh, l1cWl, 4 * C_ * C_);
    split_arr(l1_reg_w,     l1rWh, l1rWl, 4 * C_ * C_);
    split_arr(l2_cls_w,     l2cWh, l2cWl, 16 * C_ * C_);
    split_arr(l2_reg_w,     l2rWh, l2rWl, 16 * C_ * C_);

    // 1) reg branch 1x1 projection -> regp planes
    run_g<true, 3, 1>(N_, C_, D_, fRh, fRl, D_, 0, pWh, pWl, nullptr, D_, 0,
                      nullptr, rph, rpl, C_, 0, 1.f, nullptr, 1);

    // 2) QKV projections -> f32
    run_g<true, 3, 0>(N_, 3 * C_, C_, fCh, fCl, C_, 0, qcWh, qcWl, nullptr, C_, 0,
                      qkvc, nullptr, nullptr, 3 * C_, 0, 1.f, nullptr, 1);
    run_g<true, 3, 0>(N_, 3 * C_, C_, rph, rpl, C_, 0, qrWh, qrWl, nullptr, C_, 0,
                      qkvr, nullptr, nullptr, 3 * C_, 0, 1.f, nullptr, 1);

    // 3) split + normalize (scale baked into k planes)
    qkv_split_kernel<<<(N_ * H_ * 32 + 255) / 256, 256>>>(
        qkvc, qch, qcl, kch, kcl, vf, 0,  vnfc, ech, ecl, cls_scores);
    qkv_split_kernel<<<(N_ * H_ * 32 + 255) / 256, 256>>>(
        qkvr, qrh, qrl, krh, krl, vf, 64, vnfr, erh, erl, nullptr);

    // 4) attention logits per head (pre-scaled) -> f32
    run_g<true, 3, 0>(N_, N_, D_, qch, qcl, D_, QS_, kch, kcl, nullptr, D_, QS_,
                      bufA, nullptr, nullptr, N_, HS_, 1.f, nullptr, H_);
    run_g<true, 3, 0>(N_, N_, D_, qrh, qrl, D_, QS_, krh, krl, nullptr, D_, QS_,
                      bufB, nullptr, nullptr, N_, HS_, 1.f, nullptr, H_);

    // 5) fused dual softmax + average -> attn planes
    softmax_avg_kernel<<<H_ * N_, 256>>>(bufA, bufB, ath, atl);

    // 6) gram matrices, 1-pass bf16 (threshold consumers), reuse bufA/bufB
    run_g<true, 1, 0>(N_, N_, C_, vnfc, vnfc, C_, 0, vnfc, vnfc, nullptr, C_, 0,
                      bufA, nullptr, nullptr, N_, 0, 0.25f, nullptr, 1);
    run_g<true, 1, 0>(N_, N_, C_, vnfr, vnfr, C_, 0, vnfr, vnfr, nullptr, C_, 0,
                      bufB, nullptr, nullptr, N_, 0, 0.25f, nullptr, 1);

    // 7) sim_round2 + obj_mask -> sparse CSR
    sim_kernel<<<N_, 256>>>(ath, atl, bufA, bufB, sr2i, sr2v, sr2c, obji, objv, objc);

    // 8) attn @ [v_cls|v_reg] per head (NN path, B f32 split inline) -> av, scatter
    run_g<false, 3, 0>(N_, 128, N_, ath, atl, N_, HS_,
                       nullptr, nullptr, vf, 128, (size_t)N_ * 128,
                       av, nullptr, nullptr, 128, (size_t)N_ * 128, 1.f, nullptr, H_);
    scatter_av_kernel<<<(H_ * N_ * 32) / 256, 256>>>(av, ech, ecl, erh, erl);

    // 9) l1 linears -> pool planes cols [512,1024)
    run_g<true, 3, 1>(N_, 2 * C_, 2 * C_, ech, ecl, 2 * C_, 0, l1cWh, l1cWl, nullptr, 2 * C_, 0,
                      nullptr, pch + 2 * C_, pcl + 2 * C_, 4 * C_, 0, 1.f, l1_cls_b, 1);
    run_g<true, 3, 1>(N_, 2 * C_, 2 * C_, erh, erl, 2 * C_, 0, l1rWh, l1rWl, nullptr, 2 * C_, 0,
                      nullptr, prh + 2 * C_, prl + 2 * C_, 4 * C_, 0, 1.f, l1_reg_b, 1);

    // 10) pooled inter via sparse gather -> pool planes cols [0,512)
    pool_kernel<<<N_, 128>>>(sr2i, sr2v, sr2c, pch, pcl);
    pool_kernel<<<N_, 128>>>(obji, objv, objc, prh, prl);

    // 11) l2 linears -> f32 outputs
    run_g<true, 3, 0>(N_, 4 * C_, 4 * C_, pch, pcl, 4 * C_, 0, l2cWh, l2cWl, nullptr, 4 * C_, 0,
                      out, nullptr, nullptr, 4 * C_, 0, 1.f, l2_cls_b, 1);
    run_g<true, 3, 0>(N_, 4 * C_, 4 * C_, prh, prl, 4 * C_, 0, l2rWh, l2rWl, nullptr, 4 * C_, 0,
                      out + (size_t)N_ * 4 * C_, nullptr, nullptr, 4 * C_, 0, 1.f, l2_reg_b, 1);
}

// round 16
// speedup vs baseline: 1.0797x; 1.0797x over previous
#include <cuda_runtime.h>
#include <cuda_bf16.h>
#include <cstdint>
#include <cstddef>

static constexpr int    N_  = 3072;
static constexpr int    C_  = 256;
static constexpr int    H_  = 4;
static constexpr int    D_  = 64;
static constexpr size_t HS_ = (size_t)N_ * N_;
static constexpr size_t QS_ = (size_t)N_ * D_;
static constexpr int    MW_ = N_ / 32;          // mask words per row = 96

typedef __nv_bfloat16 bf;

// ---------------- device scratch ----------------
__device__ bf g_featC_h[N_ * C_],      g_featC_l[N_ * C_];
__device__ bf g_featR_h[N_ * D_],      g_featR_l[N_ * D_];
__device__ bf g_projW_h[C_ * D_],      g_projW_l[C_ * D_];
__device__ bf g_qkvcW_h[3 * C_ * C_],  g_qkvcW_l[3 * C_ * C_];
__device__ bf g_qkvrW_h[3 * C_ * C_],  g_qkvrW_l[3 * C_ * C_];
__device__ bf g_l1cW_h[4 * C_ * C_],   g_l1cW_l[4 * C_ * C_];
__device__ bf g_l1rW_h[4 * C_ * C_],   g_l1rW_l[4 * C_ * C_];
__device__ bf g_l2cW_h[16 * C_ * C_],  g_l2cW_l[16 * C_ * C_];
__device__ bf g_l2rW_h[16 * C_ * C_],  g_l2rW_l[16 * C_ * C_];
__device__ bf g_regp_h[N_ * C_],       g_regp_l[N_ * C_];
__device__ bf g_qnc_h[H_ * N_ * D_],   g_qnc_l[H_ * N_ * D_];
__device__ bf g_knc_h[H_ * N_ * D_],   g_knc_l[H_ * N_ * D_];
__device__ bf g_qnr_h[H_ * N_ * D_],   g_qnr_l[H_ * N_ * D_];
__device__ bf g_knr_h[H_ * N_ * D_],   g_knr_l[H_ * N_ * D_];
__device__ bf g_vnfc_h[N_ * C_];
__device__ bf g_vnfr_h[N_ * C_];
__device__ bf g_attn_h[(size_t)H_ * N_ * N_];
__device__ bf g_attn_l[(size_t)H_ * N_ * N_];
__device__ bf g_enhc_h[N_ * 2 * C_],   g_enhc_l[N_ * 2 * C_];
__device__ bf g_enhr_h[N_ * 2 * C_],   g_enhr_l[N_ * 2 * C_];
__device__ bf g_poolc_h[N_ * 4 * C_],  g_poolc_l[N_ * 4 * C_];
__device__ bf g_poolr_h[N_ * 4 * C_],  g_poolr_l[N_ * 4 * C_];
__device__ float g_qkv_cls[N_ * 3 * C_];
__device__ float g_qkv_reg[N_ * 3 * C_];
__device__ float g_vfused [H_ * N_ * 2 * D_];   // per head [k, 128] = [v_cls | v_reg]
__device__ float g_av     [H_ * N_ * 2 * D_];
__device__ float g_bufA[(size_t)H_ * N_ * N_];
__device__ float g_bufB[(size_t)H_ * N_ * N_];
__device__ uint32_t g_maskC[(size_t)N_ * MW_];
__device__ uint32_t g_maskR[(size_t)N_ * MW_];
__device__ float g_sr2v[(size_t)N_ * N_];
__device__ int   g_sr2i[(size_t)N_ * N_];
__device__ int   g_sr2c[N_];
__device__ float g_objv[(size_t)N_ * N_];
__device__ int   g_obji[(size_t)N_ * N_];
__device__ int   g_objc[N_];

// ---------------- primitives ----------------
__device__ __forceinline__ uint32_t cvta_shared(const void* p) {
    return (uint32_t)__cvta_generic_to_shared(p);
}
__device__ __forceinline__ void ldmatrix_x4(uint32_t& r0, uint32_t& r1,
                                            uint32_t& r2, uint32_t& r3, uint32_t addr) {
    asm volatile("ldmatrix.sync.aligned.m8n8.x4.shared.b16 {%0,%1,%2,%3}, [%4];"
                 : "=r"(r0), "=r"(r1), "=r"(r2), "=r"(r3) : "r"(addr));
}
__device__ __forceinline__ void mma_bf16(float* c, uint32_t a0, uint32_t a1,
                                         uint32_t a2, uint32_t a3,
                                         uint32_t b0, uint32_t b1) {
    asm volatile(
        "mma.sync.aligned.m16n8k16.row.col.f32.bf16.bf16.f32 "
        "{%0,%1,%2,%3}, {%4,%5,%6,%7}, {%8,%9}, {%0,%1,%2,%3};"
        : "+f"(c[0]), "+f"(c[1]), "+f"(c[2]), "+f"(c[3])
        : "r"(a0), "r"(a1), "r"(a2), "r"(a3), "r"(b0), "r"(b1));
}
__device__ __forceinline__ void split_bf16(float x, bf& h, bf& l) {
    h = __float2bfloat16_rn(x);
    l = __float2bfloat16_rn(x - __bfloat162float(h));
}

// =======================================================================================
// R12-core GEMM on pre-split hi/lo bf16 planes (validated).
//   TRANSB = true : B as hi/lo planes [N,K].  false: B as f32 [K,N] (split inline).
//   PASSES = 3: emulated-fp32.  PASSES = 1: hi only.
//   EPI: 0 = f32 C;  1 = hi/lo plane C;  2 = threshold bitmask (Cm, alpha*acc > thr).
// REQUIRES M%128==0, N%128==0, K%32==0.
// =======================================================================================
template <bool TRANSB, int PASSES, int EPI>
__global__ __launch_bounds__(256, 1)
void gemm_tc(int K,
             const bf* __restrict__ Ah, const bf* __restrict__ Al, int lda, size_t sA,
             const bf* __restrict__ Bh, const bf* __restrict__ Bl,
             const float* __restrict__ Bf, int ldb, size_t sB,
             float* __restrict__ Cf, bf* __restrict__ Ch, bf* __restrict__ Cl,
             uint32_t* __restrict__ Cm, float thr,
             int ldc, size_t sC,
             float alpha, const float* __restrict__ bias)
{
    constexpr int BM = 128, BN = 128, LDS = 24;
    constexpr int MI = 4, NI = 4;
    constexpr int TSZ = BM * LDS;
    constexpr uint32_t SUB_B = TSZ * 2;
    constexpr uint32_t BUF_B = 2 * SUB_B;

    extern __shared__ bf sm[];
    bf* AsH = sm;
    bf* AsL = sm + 4 * TSZ;
    bf* BsH = sm + 8 * TSZ;
    bf* BsL = sm + 12 * TSZ;

    const int bz = blockIdx.z;
    Ah += bz * sA;
    if (PASSES == 3) Al += bz * sA;
    if (TRANSB) {
        Bh += bz * sB;
        if (PASSES == 3) Bl += bz * sB;
    } else {
        Bf += bz * sB;
    }
    if (EPI == 0) {
        Cf += bz * sC;
    } else if (EPI == 1) {
        Ch += bz * sC;
        Cl += bz * sC;
    }

    const int m0   = blockIdx.y * BM;
    const int n0   = blockIdx.x * BN;
    const int tid  = threadIdx.x;
    const int lane = tid & 31;
    const int wid  = tid >> 5;
    const int warpN = wid & 3;
    const int warpM = wid >> 2;

    int am[4], asub[4], akin[4], agk[4];
#pragma unroll
    for (int i = 0; i < 4; i++) {
        int id = tid + i * 256;
        am[i]   = id >> 3;
        int q   = id & 7;
        asub[i] = q >> 2;
        akin[i] = (q & 3) << 2;
        agk[i]  = q << 2;
    }
    int bn[4], bsub[4], bkin[4], bgk[4];
#pragma unroll
    for (int i = 0; i < 4; i++) {
        int id = tid + i * 256;
        if (TRANSB) {
            bn[i]   = id >> 3;
            int q   = id & 7;
            bsub[i] = q >> 2;
            bkin[i] = (q & 3) << 2;
            bgk[i]  = q << 2;
        } else {
            int k   = id >> 5;
            bn[i]   = (id & 31) << 2;
            bsub[i] = k >> 4;
            bkin[i] = k & 15;
            bgk[i]  = k;
        }
    }

    const int aRow = lane & 15, aChunk = lane >> 4;
    const int bRow = ((lane >> 4) << 3) + (lane & 7), bChunk = (lane >> 3) & 1;
    uint32_t adrAH[MI], adrAL[MI], adrBH[2], adrBL[2];
#pragma unroll
    for (int mi = 0; mi < MI; mi++) {
        int row = warpM * 64 + mi * 16 + aRow;
        adrAH[mi] = cvta_shared(AsH) + row * 48 + aChunk * 16;
        adrAL[mi] = cvta_shared(AsL) + row * 48 + aChunk * 16;
    }
#pragma unroll
    for (int p = 0; p < 2; p++) {
        int row = warpN * 32 + p * 16 + bRow;
        adrBH[p] = cvta_shared(BsH) + row * 48 + bChunk * 16;
        adrBL[p] = cvta_shared(BsL) + row * 48 + bChunk * 16;
    }

    float acc[MI][NI][4];
#pragma unroll
    for (int mi = 0; mi < MI; mi++)
#pragma unroll
        for (int ni = 0; ni < NI; ni++)
#pragma unroll
            for (int j = 0; j < 4; j++) acc[mi][ni][j] = 0.f;

    uint2 ahr[4], alr[4], bhr[4], blr[4];
    float4 bfr[4];
    auto ldg = [&](int k0) {
#pragma unroll
        for (int i = 0; i < 4; i++) {
            ahr[i] = *reinterpret_cast<const uint2*>(Ah + (size_t)(m0 + am[i]) * lda + k0 + agk[i]);
            if (PASSES == 3)
                alr[i] = *reinterpret_cast<const uint2*>(Al + (size_t)(m0 + am[i]) * lda + k0 + agk[i]);
        }
        if (TRANSB) {
#pragma unroll
            for (int i = 0; i < 4; i++) {
                bhr[i] = *reinterpret_cast<const uint2*>(Bh + (size_t)(n0 + bn[i]) * ldb + k0 + bgk[i]);
                if (PASSES == 3)
                    blr[i] = *reinterpret_cast<const uint2*>(Bl + (size_t)(n0 + bn[i]) * ldb + k0 + bgk[i]);
            }
        } else {
#pragma unroll
            for (int i = 0; i < 4; i++)
                bfr[i] = *reinterpret_cast<const float4*>(Bf + (size_t)(k0 + bgk[i]) * ldb + n0 + bn[i]);
        }
    };
    auto sts = [&](int buf) {
#pragma unroll
        for (int i = 0; i < 4; i++) {
            int o = ((buf * 2 + asub[i]) * BM + am[i]) * LDS + akin[i];
            *reinterpret_cast<uint2*>(&AsH[o]) = ahr[i];
            if (PASSES == 3) *reinterpret_cast<uint2*>(&AsL[o]) = alr[i];
        }
        if (TRANSB) {
#pragma unroll
            for (int i = 0; i < 4; i++) {
                int o = ((buf * 2 + bsub[i]) * BN + bn[i]) * LDS + bkin[i];
                *reinterpret_cast<uint2*>(&BsH[o]) = bhr[i];
                if (PASSES == 3) *reinterpret_cast<uint2*>(&BsL[o]) = blr[i];
            }
        } else {
#pragma unroll
            for (int i = 0; i < 4; i++) {
                bf h0, h1, h2, h3, l0, l1, l2, l3;
                split_bf16(bfr[i].x, h0, l0); split_bf16(bfr[i].y, h1, l1);
                split_bf16(bfr[i].z, h2, l2); split_bf16(bfr[i].w, h3, l3);
                int ob = (buf * 2 + bsub[i]) * BN;
                BsH[(ob + bn[i] + 0) * LDS + bkin[i]] = h0;
                BsH[(ob + bn[i] + 1) * LDS + bkin[i]] = h1;
                BsH[(ob + bn[i] + 2) * LDS + bkin[i]] = h2;
                BsH[(ob + bn[i] + 3) * LDS + bkin[i]] = h3;
                if (PASSES == 3) {
                    BsL[(ob + bn[i] + 0) * LDS + bkin[i]] = l0;
                    BsL[(ob + bn[i] + 1) * LDS + bkin[i]] = l1;
                    BsL[(ob + bn[i] + 2) * LDS + bkin[i]] = l2;
                    BsL[(ob + bn[i] + 3) * LDS + bkin[i]] = l3;
                }
            }
        }
    };

    ldg(0);
    sts(0);
    __syncthreads();

    const int S = K >> 5;
    int buf = 0;
    for (int s = 0; s < S; s++) {
        const bool has_next = (s + 1) < S;
        if (has_next) ldg((s + 1) << 5);

#pragma unroll
        for (int sub = 0; sub < 2; sub++) {
            const uint32_t off = (uint32_t)buf * BUF_B + (uint32_t)sub * SUB_B;
            uint32_t aH[MI][4], aL[MI][4], bH[NI][2], bL[NI][2];
#pragma unroll
            for (int mi = 0; mi < MI; mi++) {
                ldmatrix_x4(aH[mi][0], aH[mi][1], aH[mi][2], aH[mi][3], adrAH[mi] + off);
                if (PASSES == 3)
                    ldmatrix_x4(aL[mi][0], aL[mi][1], aL[mi][2], aL[mi][3], adrAL[mi] + off);
            }
#pragma unroll
            for (int p = 0; p < 2; p++) {
                uint32_t r0, r1, r2, r3;
                ldmatrix_x4(r0, r1, r2, r3, adrBH[p] + off);
                bH[2 * p][0] = r0; bH[2 * p][1] = r1;
                bH[2 * p + 1][0] = r2; bH[2 * p + 1][1] = r3;
                if (PASSES == 3) {
                    ldmatrix_x4(r0, r1, r2, r3, adrBL[p] + off);
                    bL[2 * p][0] = r0; bL[2 * p][1] = r1;
                    bL[2 * p + 1][0] = r2; bL[2 * p + 1][1] = r3;
                }
            }
#pragma unroll
            for (int mi = 0; mi < MI; mi++)
#pragma unroll
                for (int ni = 0; ni < NI; ni++) {
                    mma_bf16(acc[mi][ni], aH[mi][0], aH[mi][1], aH[mi][2], aH[mi][3],
                             bH[ni][0], bH[ni][1]);
                    if (PASSES == 3) {
                        mma_bf16(acc[mi][ni], aH[mi][0], aH[mi][1], aH[mi][2], aH[mi][3],
                                 bL[ni][0], bL[ni][1]);
                        mma_bf16(acc[mi][ni], aL[mi][0], aL[mi][1], aL[mi][2], aL[mi][3],
                                 bH[ni][0], bH[ni][1]);
                    }
                }
        }

        if (has_next) {
            sts(buf ^ 1);
            __syncthreads();
            buf ^= 1;
        }
    }

    const int g = lane >> 2, t = lane & 3;

    if (EPI == 2) {
        // threshold bitmask epilogue: assemble 128x128 bits in smem, write owned words.
        __syncthreads();
        uint32_t* smask = reinterpret_cast<uint32_t*>(sm);
        for (int i = tid; i < 512; i += 256) smask[i] = 0u;
        __syncthreads();
#pragma unroll
        for (int mi = 0; mi < MI; mi++)
#pragma unroll
            for (int ni = 0; ni < NI; ni++) {
                int cl = warpN * 32 + ni * 8 + t * 2;
                int rl = warpM * 64 + mi * 16 + g;
                uint32_t b0 = ((alpha * acc[mi][ni][0] > thr) ? 1u : 0u) |
                              ((alpha * acc[mi][ni][1] > thr) ? 2u : 0u);
                uint32_t b1 = ((alpha * acc[mi][ni][2] > thr) ? 1u : 0u) |
                              ((alpha * acc[mi][ni][3] > thr) ? 2u : 0u);
                if (b0) atomicOr(&smask[rl * 4 + (cl >> 5)], b0 << (cl & 31));
                if (b1) atomicOr(&smask[(rl + 8) * 4 + (cl >> 5)], b1 << (cl & 31));
            }
        __syncthreads();
        for (int i = tid; i < 512; i += 256) {
            int r = i >> 2, w = i & 3;
            Cm[(size_t)(m0 + r) * MW_ + (n0 >> 5) + w] = smask[i];
        }
        return;
    }

#pragma unroll
    for (int mi = 0; mi < MI; mi++) {
#pragma unroll
        for (int ni = 0; ni < NI; ni++) {
            int col = n0 + warpN * 32 + ni * 8 + t * 2;
            int r0  = m0 + warpM * 64 + mi * 16 + g;
            float2 o0, o1;
            o0.x = alpha * acc[mi][ni][0];
            o0.y = alpha * acc[mi][ni][1];
            o1.x = alpha * acc[mi][ni][2];
            o1.y = alpha * acc[mi][ni][3];
            if (bias) {
                float2 bv = *reinterpret_cast<const float2*>(bias + col);
                o0.x += bv.x; o0.y += bv.y;
                o1.x += bv.x; o1.y += bv.y;
            }
            if (EPI == 0) {
                *reinterpret_cast<float2*>(Cf + (size_t)r0 * ldc + col)       = o0;
                *reinterpret_cast<float2*>(Cf + (size_t)(r0 + 8) * ldc + col) = o1;
            } else {
                bf h0, l0, h1, l1;
                split_bf16(o0.x, h0, l0); split_bf16(o0.y, h1, l1);
                *reinterpret_cast<__nv_bfloat162*>(Ch + (size_t)r0 * ldc + col) = __nv_bfloat162(h0, h1);
                *reinterpret_cast<__nv_bfloat162*>(Cl + (size_t)r0 * ldc + col) = __nv_bfloat162(l0, l1);
                split_bf16(o1.x, h0, l0); split_bf16(o1.y, h1, l1);
                *reinterpret_cast<__nv_bfloat162*>(Ch + (size_t)(r0 + 8) * ldc + col) = __nv_bfloat162(h0, h1);
                *reinterpret_cast<__nv_bfloat162*>(Cl + (size_t)(r0 + 8) * ldc + col) = __nv_bfloat162(l0, l1);
            }
        }
    }
}

static constexpr int GEMM_SMEM = 16 * 128 * 24 * 2;   // 98304 bytes

template <bool TRANSB, int PASSES, int EPI>
static void run_g(int M, int N, int K,
                  const bf* Ah, const bf* Al, int lda, size_t sA,
                  const bf* Bh, const bf* Bl, const float* Bf, int ldb, size_t sB,
                  float* Cf, bf* Ch, bf* Cl, uint32_t* Cm, float thr,
                  int ldc, size_t sC,
                  float alpha, const float* bias, int batch)
{
    dim3 grid(N / 128, M / 128, batch);
    gemm_tc<TRANSB, PASSES, EPI><<<grid, 256, GEMM_SMEM>>>(
        K, Ah, Al, lda, sA, Bh, Bl, Bf, ldb, sB, Cf, Ch, Cl, Cm, thr, ldc, sC, alpha, bias);
}

// ---------------- reductions ----------------
__device__ __forceinline__ float warpSum(float v) {
#pragma unroll
    for (int o = 16; o; o >>= 1) v += __shfl_xor_sync(0xffffffffu, v, o);
    return v;
}
__device__ __forceinline__ float warpMax(float v) {
#pragma unroll
    for (int o = 16; o; o >>= 1) v = fmaxf(v, __shfl_xor_sync(0xffffffffu, v, o));
    return v;
}
__device__ __forceinline__ float blockMax(float v, float* red) {
    v = warpMax(v);
    if ((threadIdx.x & 31) == 0) red[threadIdx.x >> 5] = v;
    __syncthreads();
    float r = red[0];
#pragma unroll
    for (int i = 1; i < 8; i++) r = fmaxf(r, red[i]);
    __syncthreads();
    return r;
}
__device__ __forceinline__ float blockSum(float v, float* red) {
    v = warpSum(v);
    if ((threadIdx.x & 31) == 0) red[threadIdx.x >> 5] = v;
    __syncthreads();
    float r = red[0];
#pragma unroll
    for (int i = 1; i < 8; i++) r += red[i];
    __syncthreads();
    return r;
}

// ---------------- elementwise kernels ----------------
__global__ void split_arr_kernel(const float* __restrict__ s,
                                 bf* __restrict__ h, bf* __restrict__ l, int n)
{
    int t = blockIdx.x * 256 + threadIdx.x;
    if (t < n) {
        bf hh, ll;
        split_bf16(s[t], hh, ll);
        h[t] = hh; l[t] = ll;
    }
}

__global__ void qkv_split_kernel(const float* __restrict__ qkv,
                                 bf* __restrict__ qh, bf* __restrict__ ql,
                                 bf* __restrict__ kh, bf* __restrict__ kl,
                                 float* __restrict__ vf, int coloff,
                                 bf* __restrict__ vnfh,
                                 bf* __restrict__ ehh, bf* __restrict__ ehl,
                                 const float* __restrict__ scores)
{
    int w = (blockIdx.x * blockDim.x + threadIdx.x) >> 5;
    if (w >= N_ * H_) return;
    int lane = threadIdx.x & 31;
    int h = w & 3;
    int n = w >> 2;

    const float* src = qkv + (size_t)n * (3 * C_) + h * D_;
    float q0 = src[lane],            q1 = src[lane + 32];
    float k0 = src[C_ + lane],       k1 = src[C_ + lane + 32];
    float v0 = src[2 * C_ + lane],   v1 = src[2 * C_ + lane + 32];

    float sq = warpSum(q0 * q0 + q1 * q1);
    float sk = warpSum(k0 * k0 + k1 * k1);
    float sv = warpSum(v0 * v0 + v1 * v1);
    float iq = 1.f / fmaxf(sqrtf(sq), 1e-6f);
    float ik = 1.f / fmaxf(sqrtf(sk), 1e-6f);
    float iv = 1.f / fmaxf(sqrtf(sv), 1e-6f);
    float ks = (scores ? 25.f * scores[n] : 25.f) * ik;

    size_t ho = ((size_t)h * N_ + n) * D_;
    bf hh, ll;
    split_bf16(q0 * iq, hh, ll); qh[ho + lane] = hh;      ql[ho + lane] = ll;
    split_bf16(q1 * iq, hh, ll); qh[ho + lane + 32] = hh; ql[ho + lane + 32] = ll;
    split_bf16(k0 * ks, hh, ll); kh[ho + lane] = hh;      kl[ho + lane] = ll;
    split_bf16(k1 * ks, hh, ll); kh[ho + lane + 32] = hh; kl[ho + lane + 32] = ll;

    size_t vo = ((size_t)h * N_ + n) * (2 * D_) + coloff;
    vf[vo + lane] = v0; vf[vo + lane + 32] = v1;

    size_t fo = (size_t)n * C_ + h * D_;
    vnfh[fo + lane]      = __float2bfloat16_rn(v0 * iv);
    vnfh[fo + lane + 32] = __float2bfloat16_rn(v1 * iv);

    size_t eo = (size_t)n * (2 * C_) + C_ + h * D_;
    split_bf16(v0, hh, ll); ehh[eo + lane] = hh;      ehl[eo + lane] = ll;
    split_bf16(v1, hh, ll); ehh[eo + lane + 32] = hh; ehl[eo + lane + 32] = ll;
}

__global__ void softmax_avg_kernel(const float* __restrict__ lc_all,
                                   const float* __restrict__ lr_all,
                                   bf* __restrict__ ah, bf* __restrict__ al)
{
    __shared__ float sc[N_];
    __shared__ float sr[N_];
    __shared__ float red[8];
    size_t base = (size_t)blockIdx.x * N_;
    const float* lc = lc_all + base;
    const float* lr = lr_all + base;

    float mc = -3.4e38f, mr = -3.4e38f;
    for (int m = threadIdx.x; m < N_; m += 256) {
        float xc = lc[m], xr = lr[m];
        sc[m] = xc; sr[m] = xr;
        mc = fmaxf(mc, xc); mr = fmaxf(mr, xr);
    }
    mc = blockMax(mc, red);
    mr = blockMax(mr, red);

    float tc = 0.f, tr = 0.f;
    for (int m = threadIdx.x; m < N_; m += 256) {
        float ec = expf(sc[m] - mc);
        float er = expf(sr[m] - mr);
        sc[m] = ec; sr[m] = er;
        tc += ec; tr += er;
    }
    tc = blockSum(tc, red);
    tr = blockSum(tr, red);

    float ic = 0.5f / tc, ir = 0.5f / tr;
    for (int m = threadIdx.x; m < N_; m += 256) {
        bf hh, ll;
        split_bf16(sc[m] * ic + sr[m] * ir, hh, ll);
        ah[base + m] = hh; al[base + m] = ll;
    }
}

// =======================================================================================
// Sparse sim: one warp per row. Scan cls bitmask (ascending m, deterministic); gather
// head-mean attn at set bits; sr2 = exp(s)/sum (max & softmax denom cancel exactly);
// obj = (reg bit) * sr2 / sum(sr2).  Diagonal bit is always set (gram[n][n]=1).
// =======================================================================================
__global__ __launch_bounds__(256)
void sim_sparse_kernel(const bf* __restrict__ ah, const bf* __restrict__ al,
                       const uint32_t* __restrict__ maskC,
                       const uint32_t* __restrict__ maskR,
                       int*  __restrict__ s_idx, float* __restrict__ s_val,
                       int*  __restrict__ s_cnt,
                       int*  __restrict__ o_idx, float* __restrict__ o_val,
                       int*  __restrict__ o_cnt)
{
    int warp = (blockIdx.x * 256 + threadIdx.x) >> 5;
    if (warp >= N_) return;
    int lane = threadIdx.x & 31;
    int n = warp;
    size_t ro = (size_t)n * N_;
    const uint32_t* mc = maskC + (size_t)n * MW_;
    const uint32_t* mr = maskR + (size_t)n * MW_;
    unsigned ltm = (lane == 0) ? 0u : (0xffffffffu >> (32 - lane));

    // pass 1: compact positions ascending, store e = exp(s), accumulate sum
    int cnt = 0;
    float sumE = 0.f;
#pragma unroll
    for (int c = 0; c < 3; c++) {
        uint32_t w = mc[c * 32 + lane];
        int nb = __popc(w);
        int x = nb;
#pragma unroll
        for (int o = 1; o < 32; o <<= 1) {
            int y = __shfl_up_sync(0xffffffffu, x, o);
            if (lane >= o) x += y;
        }
        int off = x - nb;
        int tot = __shfl_sync(0xffffffffu, x, 31);
        uint32_t ww = w;
        int j = 0;
        while (ww) {
            int b = __ffs(ww) - 1;
            ww &= ww - 1;
            int m = (c * 32 + lane) * 32 + b;
            float s = 0.f;
#pragma unroll
            for (int h = 0; h < 4; h++) {
                size_t o2 = (size_t)h * HS_ + ro + m;
                s += __bfloat162float(ah[o2]) + __bfloat162float(al[o2]);
            }
            s *= 0.25f;
            float e = expf(s);
            s_idx[ro + cnt + off + j] = m;
            s_val[ro + cnt + off + j] = e;
            sumE += e;
            j++;
        }
        cnt += tot;
    }
    sumE = warpSum(sumE);
    float inv = 1.f / sumE;
    __syncwarp();

    // pass 2: normalize; accumulate S2 (== sum of sr2, matches reference fp handling)
    float s2 = 0.f;
    for (int i = lane; i < cnt; i += 32) {
        float v = s_val[ro + i] * inv;
        s_val[ro + i] = v;
        s2 += v;
    }
    s2 = warpSum(s2);
    float inv2 = 1.f / s2;
    __syncwarp();

    // pass 3: obj compaction (ascending, deterministic)
    int oc = 0;
    for (int i0 = 0; i0 < cnt; i0 += 32) {
        int i = i0 + lane;
        bool keep = false;
        int m = 0; float v = 0.f;
        if (i < cnt) {
            m = s_idx[ro + i];
            v = s_val[ro + i];
            keep = (mr[m >> 5] >> (m & 31)) & 1u;
        }
        unsigned bal = __ballot_sync(0xffffffffu, keep);
        if (keep) {
            int p = oc + __popc(bal & ltm);
            o_idx[ro + p] = m;
            o_val[ro + p] = v * inv2;
        }
        oc += __popc(bal);
    }
    if (lane == 0) { s_cnt[n] = cnt; o_cnt[n] = oc; }
}

// sparse pooled mix on bf16 hi/lo pool planes (reads cols 512:1024, writes 0:512)
__global__ __launch_bounds__(128)
void pool_kernel(const int* __restrict__ idx, const float* __restrict__ val,
                 const int* __restrict__ cnt,
                 bf* __restrict__ ph, bf* __restrict__ pl)
{
    int n = blockIdx.x;
    int k = cnt[n];
    size_t ro = (size_t)n * N_;
    int c = threadIdx.x * 4;

    float acc[4] = {0.f, 0.f, 0.f, 0.f};
    for (int j = 0; j < k; j++) {
        int   m = idx[ro + j];
        float w = val[ro + j];
        size_t o = (size_t)m * 1024 + 512 + c;
        __nv_bfloat162 h0 = *reinterpret_cast<const __nv_bfloat162*>(ph + o);
        __nv_bfloat162 h1 = *reinterpret_cast<const __nv_bfloat162*>(ph + o + 2);
        __nv_bfloat162 l0 = *reinterpret_cast<const __nv_bfloat162*>(pl + o);
        __nv_bfloat162 l1 = *reinterpret_cast<const __nv_bfloat162*>(pl + o + 2);
        acc[0] += w * (__bfloat162float(h0.x) + __bfloat162float(l0.x));
        acc[1] += w * (__bfloat162float(h0.y) + __bfloat162float(l0.y));
        acc[2] += w * (__bfloat162float(h1.x) + __bfloat162float(l1.x));
        acc[3] += w * (__bfloat162float(h1.y) + __bfloat162float(l1.y));
    }
    size_t o = (size_t)n * 1024 + c;
    bf h0, l0, h1, l1;
    split_bf16(acc[0], h0, l0); split_bf16(acc[1], h1, l1);
    *reinterpret_cast<__nv_bfloat162*>(ph + o)     = __nv_bfloat162(h0, h1);
    *reinterpret_cast<__nv_bfloat162*>(pl + o)     = __nv_bfloat162(l0, l1);
    split_bf16(acc[2], h0, l0); split_bf16(acc[3], h1, l1);
    *reinterpret_cast<__nv_bfloat162*>(ph + o + 2) = __nv_bfloat162(h0, h1);
    *reinterpret_cast<__nv_bfloat162*>(pl + o + 2) = __nv_bfloat162(l0, l1);
}

// scatter av f32 [h][n][128] into enh inter halves (hi/lo planes)
__global__ __launch_bounds__(256)
void scatter_av_kernel(const float* __restrict__ av,
                       bf* __restrict__ ech, bf* __restrict__ ecl,
                       bf* __restrict__ erh, bf* __restrict__ erl)
{
    int t = blockIdx.x * 256 + threadIdx.x;
    int h   = t / (N_ * 32);
    int rem = t - h * (N_ * 32);
    int n   = rem >> 5;
    int q   = rem & 31;
    float4 v = *reinterpret_cast<const float4*>(av + ((size_t)h * N_ + n) * 128 + q * 4);
    bf* dh; bf* dl; int col;
    if (q < 16) { dh = ech; dl = ecl; col = h * 64 + q * 4; }
    else        { dh = erh; dl = erl; col = h * 64 + (q - 16) * 4; }
    size_t o = (size_t)n * 512 + col;
    bf h0, l0, h1, l1;
    split_bf16(v.x, h0, l0); split_bf16(v.y, h1, l1);
    *reinterpret_cast<__nv_bfloat162*>(dh + o)     = __nv_bfloat162(h0, h1);
    *reinterpret_cast<__nv_bfloat162*>(dl + o)     = __nv_bfloat162(l0, l1);
    split_bf16(v.z, h0, l0); split_bf16(v.w, h1, l1);
    *reinterpret_cast<__nv_bfloat162*>(dh + o + 2) = __nv_bfloat162(h0, h1);
    *reinterpret_cast<__nv_bfloat162*>(dl + o + 2) = __nv_bfloat162(l0, l1);
}

static void split_arr(const float* s, bf* h, bf* l, int n)
{
    split_arr_kernel<<<(n + 255) / 256, 256>>>(s, h, l, n);
}
template <typename T>
static T* sym(const void* s) { void* p; cudaGetSymbolAddress(&p, s); return (T*)p; }

extern "C" void kernel_launch(void* const* d_in, const int* in_sizes, int n_in,
                              void* d_out, int out_size)
{
    (void)in_sizes; (void)n_in; (void)out_size;

    cudaFuncSetAttribute(gemm_tc<true, 3, 0>,  cudaFuncAttributeMaxDynamicSharedMemorySize, GEMM_SMEM);
    cudaFuncSetAttribute(gemm_tc<true, 3, 1>,  cudaFuncAttributeMaxDynamicSharedMemorySize, GEMM_SMEM);
    cudaFuncSetAttribute(gemm_tc<true, 1, 2>,  cudaFuncAttributeMaxDynamicSharedMemorySize, GEMM_SMEM);
    cudaFuncSetAttribute(gemm_tc<false, 3, 0>, cudaFuncAttributeMaxDynamicSharedMemorySize, GEMM_SMEM);

    const float* cls_features = (const float*)d_in[0];
    const float* reg_features = (const float*)d_in[1];
    const float* cls_scores   = (const float*)d_in[2];
    const float* reg_proj_w   = (const float*)d_in[3];
    const float* qkv_cls_w    = (const float*)d_in[4];
    const float* qkv_reg_w    = (const float*)d_in[5];
    const float* l1_cls_w     = (const float*)d_in[6];
    const float* l1_cls_b     = (const float*)d_in[7];
    const float* l1_reg_w     = (const float*)d_in[8];
    const float* l1_reg_b     = (const float*)d_in[9];
    const float* l2_cls_w     = (const float*)d_in[10];
    const float* l2_cls_b     = (const float*)d_in[11];
    const float* l2_reg_w     = (const float*)d_in[12];
    const float* l2_reg_b     = (const float*)d_in[13];
    float* out = (float*)d_out;

    bf *fCh = sym<bf>(g_featC_h), *fCl = sym<bf>(g_featC_l);
    bf *fRh = sym<bf>(g_featR_h), *fRl = sym<bf>(g_featR_l);
    bf *pWh = sym<bf>(g_projW_h), *pWl = sym<bf>(g_projW_l);
    bf *qcWh = sym<bf>(g_qkvcW_h), *qcWl = sym<bf>(g_qkvcW_l);
    bf *qrWh = sym<bf>(g_qkvrW_h), *qrWl = sym<bf>(g_qkvrW_l);
    bf *l1cWh = sym<bf>(g_l1cW_h), *l1cWl = sym<bf>(g_l1cW_l);
    bf *l1rWh = sym<bf>(g_l1rW_h), *l1rWl = sym<bf>(g_l1rW_l);
    bf *l2cWh = sym<bf>(g_l2cW_h), *l2cWl = sym<bf>(g_l2cW_l);
    bf *l2rWh = sym<bf>(g_l2rW_h), *l2rWl = sym<bf>(g_l2rW_l);
    bf *rph = sym<bf>(g_regp_h),  *rpl = sym<bf>(g_regp_l);
    bf *qch = sym<bf>(g_qnc_h), *qcl = sym<bf>(g_qnc_l);
    bf *kch = sym<bf>(g_knc_h), *kcl = sym<bf>(g_knc_l);
    bf *qrh = sym<bf>(g_qnr_h), *qrl = sym<bf>(g_qnr_l);
    bf *krh = sym<bf>(g_knr_h), *krl = sym<bf>(g_knr_l);
    bf *vnfc = sym<bf>(g_vnfc_h), *vnfr = sym<bf>(g_vnfr_h);
    bf *ath = sym<bf>(g_attn_h), *atl = sym<bf>(g_attn_l);
    bf *ech = sym<bf>(g_enhc_h), *ecl = sym<bf>(g_enhc_l);
    bf *erh = sym<bf>(g_enhr_h), *erl = sym<bf>(g_enhr_l);
    bf *pch = sym<bf>(g_poolc_h), *pcl = sym<bf>(g_poolc_l);
    bf *prh = sym<bf>(g_poolr_h), *prl = sym<bf>(g_poolr_l);
    float *qkvc = sym<float>(g_qkv_cls), *qkvr = sym<float>(g_qkv_reg);
    float *vf = sym<float>(g_vfused), *av = sym<float>(g_av);
    float *bufA = sym<float>(g_bufA), *bufB = sym<float>(g_bufB);
    uint32_t *mC = sym<uint32_t>(g_maskC), *mR = sym<uint32_t>(g_maskR);
    float *sr2v = sym<float>(g_sr2v), *objv = sym<float>(g_objv);
    int *sr2i = sym<int>(g_sr2i), *sr2c = sym<int>(g_sr2c);
    int *obji = sym<int>(g_obji), *objc = sym<int>(g_objc);

    // 0) pre-split inputs & weights into hi/lo bf16 planes
    split_arr(cls_features, fCh, fCl, N_ * C_);
    split_arr(reg_features, fRh, fRl, N_ * D_);
    split_arr(reg_proj_w,   pWh, pWl, C_ * D_);
    split_arr(qkv_cls_w,    qcWh, qcWl, 3 * C_ * C_);
    split_arr(qkv_reg_w,    qrWh, qrWl, 3 * C_ * C_);
    split_arr(l1_cls_w,     l1cWh, l1cWl, 4 * C_ * C_);
    split_arr(l1_reg_w,     l1rWh, l1rWl, 4 * C_ * C_);
    split_arr(l2_cls_w,     l2cWh, l2cWl, 16 * C_ * C_);
    split_arr(l2_reg_w,     l2rWh, l2rWl, 16 * C_ * C_);

    // 1) reg branch 1x1 projection -> regp planes
    run_g<true, 3, 1>(N_, C_, D_, fRh, fRl, D_, 0, pWh, pWl, nullptr, D_, 0,
                      nullptr, rph, rpl, nullptr, 0.f, C_, 0, 1.f, nullptr, 1);

    // 2) QKV projections -> f32
    run_g<true, 3, 0>(N_, 3 * C_, C_, fCh, fCl, C_, 0, qcWh, qcWl, nullptr, C_, 0,
                      qkvc, nullptr, nullptr, nullptr, 0.f, 3 * C_, 0, 1.f, nullptr, 1);
    run_g<true, 3, 0>(N_, 3 * C_, C_, rph, rpl, C_, 0, qrWh, qrWl, nullptr, C_, 0,
                      qkvr, nullptr, nullptr, nullptr, 0.f, 3 * C_, 0, 1.f, nullptr, 1);

    // 3) split + normalize (scale baked into k planes)
    qkv_split_kernel<<<(N_ * H_ * 32 + 255) / 256, 256>>>(
        qkvc, qch, qcl, kch, kcl, vf, 0,  vnfc, ech, ecl, cls_scores);
    qkv_split_kernel<<<(N_ * H_ * 32 + 255) / 256, 256>>>(
        qkvr, qrh, qrl, krh, krl, vf, 64, vnfr, erh, erl, nullptr);

    // 4) attention logits per head (pre-scaled) -> f32
    run_g<true, 3, 0>(N_, N_, D_, qch, qcl, D_, QS_, kch, kcl, nullptr, D_, QS_,
                      bufA, nullptr, nullptr, nullptr, 0.f, N_, HS_, 1.f, nullptr, H_);
    run_g<true, 3, 0>(N_, N_, D_, qrh, qrl, D_, QS_, krh, krl, nullptr, D_, QS_,
                      bufB, nullptr, nullptr, nullptr, 0.f, N_, HS_, 1.f, nullptr, H_);

    // 5) fused dual softmax + average -> attn planes
    softmax_avg_kernel<<<H_ * N_, 256>>>(bufA, bufB, ath, atl);

    // 6) gram matrices, 1-pass bf16 -> threshold BITMASKS (no N^2 f32 traffic)
    run_g<true, 1, 2>(N_, N_, C_, vnfc, vnfc, C_, 0, vnfc, vnfc, nullptr, C_, 0,
                      nullptr, nullptr, nullptr, mC, 0.75f, N_, 0, 0.25f, nullptr, 1);
    run_g<true, 1, 2>(N_, N_, C_, vnfr, vnfr, C_, 0, vnfr, vnfr, nullptr, C_, 0,
                      nullptr, nullptr, nullptr, mR, 0.99f, N_, 0, 0.25f, nullptr, 1);

    // 7) sparse sim: bitmask scan + gather attn at set bits -> CSR lists
    sim_sparse_kernel<<<(N_ * 32 + 255) / 256, 256>>>(
        ath, atl, mC, mR, sr2i, sr2v, sr2c, obji, objv, objc);

    // 8) attn @ [v_cls|v_reg] per head (NN path, B f32 split inline) -> av, scatter
    run_g<false, 3, 0>(N_, 128, N_, ath, atl, N_, HS_,
                       nullptr, nullptr, vf, 128, (size_t)N_ * 128,
                       av, nullptr, nullptr, nullptr, 0.f, 128, (size_t)N_ * 128,
                       1.f, nullptr, H_);
    scatter_av_kernel<<<(H_ * N_ * 32) / 256, 256>>>(av, ech, ecl, erh, erl);

    // 9) l1 linears -> pool planes cols [512,1024)
    run_g<true, 3, 1>(N_, 2 * C_, 2 * C_, ech, ecl, 2 * C_, 0, l1cWh, l1cWl, nullptr, 2 * C_, 0,
                      nullptr, pch + 2 * C_, pcl + 2 * C_, nullptr, 0.f, 4 * C_, 0, 1.f, l1_cls_b, 1);
    run_g<true, 3, 1>(N_, 2 * C_, 2 * C_, erh, erl, 2 * C_, 0, l1rWh, l1rWl, nullptr, 2 * C_, 0,
                      nullptr, prh + 2 * C_, prl + 2 * C_, nullptr, 0.f, 4 * C_, 0, 1.f, l1_reg_b, 1);

    // 10) pooled inter via sparse gather -> pool planes cols [0,512)
    pool_kernel<<<N_, 128>>>(sr2i, sr2v, sr2c, pch, pcl);
    pool_kernel<<<N_, 128>>>(obji, objv, objc, prh, prl);

    // 11) l2 linears -> f32 outputs
    run_g<true, 3, 0>(N_, 4 * C_, 4 * C_, pch, pcl, 4 * C_, 0, l2cWh, l2cWl, nullptr, 4 * C_, 0,
                      out, nullptr, nullptr, nullptr, 0.f, 4 * C_, 0, 1.f, l2_cls_b, 1);
    run_g<true, 3, 0>(N_, 4 * C_, 4 * C_, prh, prl, 4 * C_, 0, l2rWh, l2rWl, nullptr, 4 * C_, 0,
                      out + (size_t)N_ * 4 * C_, nullptr, nullptr, nullptr, 0.f, 4 * C_, 0,
                      1.f, l2_reg_b, 1);
}

// round 17
// speedup vs baseline: 1.1440x; 1.0596x over previous
#include <cuda_runtime.h>
#include <cuda_bf16.h>
#include <cstdint>
#include <cstddef>

static constexpr int    N_  = 3072;
static constexpr int    C_  = 256;
static constexpr int    H_  = 4;
static constexpr int    D_  = 64;
static constexpr size_t HS_ = (size_t)N_ * N_;
static constexpr size_t QS_ = (size_t)N_ * D_;
static constexpr int    MW_ = N_ / 32;          // mask words per row = 96

typedef __nv_bfloat16 bf;

// ---------------- device scratch ----------------
__device__ bf g_featC_h[N_ * C_],      g_featC_l[N_ * C_];
__device__ bf g_featR_h[N_ * D_],      g_featR_l[N_ * D_];
__device__ bf g_projW_h[C_ * D_],      g_projW_l[C_ * D_];
__device__ bf g_qkvcW_h[3 * C_ * C_],  g_qkvcW_l[3 * C_ * C_];
__device__ bf g_qkvrW_h[3 * C_ * C_],  g_qkvrW_l[3 * C_ * C_];
__device__ bf g_l1cW_h[4 * C_ * C_],   g_l1cW_l[4 * C_ * C_];
__device__ bf g_l1rW_h[4 * C_ * C_],   g_l1rW_l[4 * C_ * C_];
__device__ bf g_l2cW_h[16 * C_ * C_],  g_l2cW_l[16 * C_ * C_];
__device__ bf g_l2rW_h[16 * C_ * C_],  g_l2rW_l[16 * C_ * C_];
__device__ bf g_regp_h[N_ * C_],       g_regp_l[N_ * C_];
__device__ bf g_qnc_h[H_ * N_ * D_],   g_qnc_l[H_ * N_ * D_];
__device__ bf g_knc_h[H_ * N_ * D_],   g_knc_l[H_ * N_ * D_];
__device__ bf g_qnr_h[H_ * N_ * D_],   g_qnr_l[H_ * N_ * D_];
__device__ bf g_knr_h[H_ * N_ * D_],   g_knr_l[H_ * N_ * D_];
__device__ bf g_vnfc_h[N_ * C_];
__device__ bf g_vnfr_h[N_ * C_];
__device__ bf g_attn_h[(size_t)H_ * N_ * N_];
__device__ bf g_attn_l[(size_t)H_ * N_ * N_];
__device__ bf g_enhc_h[N_ * 2 * C_],   g_enhc_l[N_ * 2 * C_];
__device__ bf g_enhr_h[N_ * 2 * C_],   g_enhr_l[N_ * 2 * C_];
__device__ bf g_poolc_h[N_ * 4 * C_],  g_poolc_l[N_ * 4 * C_];
__device__ bf g_poolr_h[N_ * 4 * C_],  g_poolr_l[N_ * 4 * C_];
__device__ float g_qkv_cls[N_ * 3 * C_];
__device__ float g_qkv_reg[N_ * 3 * C_];
__device__ float g_vfused [H_ * N_ * 2 * D_];   // per head [k, 128] = [v_cls | v_reg]
__device__ float g_av     [H_ * N_ * 2 * D_];
__device__ float g_bufA[(size_t)H_ * N_ * N_];
__device__ float g_bufB[(size_t)H_ * N_ * N_];
__device__ uint32_t g_maskC[(size_t)N_ * MW_];
__device__ uint32_t g_maskR[(size_t)N_ * MW_];
__device__ float g_sr2v[(size_t)N_ * N_];
__device__ int   g_sr2i[(size_t)N_ * N_];
__device__ int   g_sr2c[N_];
__device__ float g_objv[(size_t)N_ * N_];
__device__ int   g_obji[(size_t)N_ * N_];
__device__ int   g_objc[N_];

// ---------------- primitives ----------------
__device__ __forceinline__ uint32_t cvta_shared(const void* p) {
    return (uint32_t)__cvta_generic_to_shared(p);
}
__device__ __forceinline__ void ldmatrix_x4(uint32_t& r0, uint32_t& r1,
                                            uint32_t& r2, uint32_t& r3, uint32_t addr) {
    asm volatile("ldmatrix.sync.aligned.m8n8.x4.shared.b16 {%0,%1,%2,%3}, [%4];"
                 : "=r"(r0), "=r"(r1), "=r"(r2), "=r"(r3) : "r"(addr));
}
__device__ __forceinline__ void mma_bf16(float* c, uint32_t a0, uint32_t a1,
                                         uint32_t a2, uint32_t a3,
                                         uint32_t b0, uint32_t b1) {
    asm volatile(
        "mma.sync.aligned.m16n8k16.row.col.f32.bf16.bf16.f32 "
        "{%0,%1,%2,%3}, {%4,%5,%6,%7}, {%8,%9}, {%0,%1,%2,%3};"
        : "+f"(c[0]), "+f"(c[1]), "+f"(c[2]), "+f"(c[3])
        : "r"(a0), "r"(a1), "r"(a2), "r"(a3), "r"(b0), "r"(b1));
}
__device__ __forceinline__ void split_bf16(float x, bf& h, bf& l) {
    h = __float2bfloat16_rn(x);
    l = __float2bfloat16_rn(x - __bfloat162float(h));
}

// =======================================================================================
// R12-core GEMM on pre-split hi/lo bf16 planes (validated).
//   TRANSB = true : B as hi/lo planes [N,K].  false: B as f32 [K,N] (split inline).
//   PASSES = 3: emulated-fp32.  PASSES = 1: hi only.
//   EPI: 0 = f32 C;  1 = hi/lo plane C;  2 = threshold bitmask (Cm, alpha*acc > thr).
// REQUIRES M%128==0, N%128==0, K%32==0.
// =======================================================================================
template <bool TRANSB, int PASSES, int EPI>
__global__ __launch_bounds__(256, 1)
void gemm_tc(int K,
             const bf* __restrict__ Ah, const bf* __restrict__ Al, int lda, size_t sA,
             const bf* __restrict__ Bh, const bf* __restrict__ Bl,
             const float* __restrict__ Bf, int ldb, size_t sB,
             float* __restrict__ Cf, bf* __restrict__ Ch, bf* __restrict__ Cl,
             uint32_t* __restrict__ Cm, float thr,
             int ldc, size_t sC,
             float alpha, const float* __restrict__ bias)
{
    constexpr int BM = 128, BN = 128, LDS = 24;
    constexpr int MI = 4, NI = 4;
    constexpr int TSZ = BM * LDS;
    constexpr uint32_t SUB_B = TSZ * 2;
    constexpr uint32_t BUF_B = 2 * SUB_B;

    extern __shared__ bf sm[];
    bf* AsH = sm;
    bf* AsL = sm + 4 * TSZ;
    bf* BsH = sm + 8 * TSZ;
    bf* BsL = sm + 12 * TSZ;

    const int bz = blockIdx.z;
    Ah += bz * sA;
    if (PASSES == 3) Al += bz * sA;
    if (TRANSB) {
        Bh += bz * sB;
        if (PASSES == 3) Bl += bz * sB;
    } else {
        Bf += bz * sB;
    }
    if (EPI == 0) {
        Cf += bz * sC;
    } else if (EPI == 1) {
        Ch += bz * sC;
        Cl += bz * sC;
    }

    const int m0   = blockIdx.y * BM;
    const int n0   = blockIdx.x * BN;
    const int tid  = threadIdx.x;
    const int lane = tid & 31;
    const int wid  = tid >> 5;
    const int warpN = wid & 3;
    const int warpM = wid >> 2;

    int am[4], asub[4], akin[4], agk[4];
#pragma unroll
    for (int i = 0; i < 4; i++) {
        int id = tid + i * 256;
        am[i]   = id >> 3;
        int q   = id & 7;
        asub[i] = q >> 2;
        akin[i] = (q & 3) << 2;
        agk[i]  = q << 2;
    }
    int bn[4], bsub[4], bkin[4], bgk[4];
#pragma unroll
    for (int i = 0; i < 4; i++) {
        int id = tid + i * 256;
        if (TRANSB) {
            bn[i]   = id >> 3;
            int q   = id & 7;
            bsub[i] = q >> 2;
            bkin[i] = (q & 3) << 2;
            bgk[i]  = q << 2;
        } else {
            int k   = id >> 5;
            bn[i]   = (id & 31) << 2;
            bsub[i] = k >> 4;
            bkin[i] = k & 15;
            bgk[i]  = k;
        }
    }

    const int aRow = lane & 15, aChunk = lane >> 4;
    const int bRow = ((lane >> 4) << 3) + (lane & 7), bChunk = (lane >> 3) & 1;
    uint32_t adrAH[MI], adrAL[MI], adrBH[2], adrBL[2];
#pragma unroll
    for (int mi = 0; mi < MI; mi++) {
        int row = warpM * 64 + mi * 16 + aRow;
        adrAH[mi] = cvta_shared(AsH) + row * 48 + aChunk * 16;
        adrAL[mi] = cvta_shared(AsL) + row * 48 + aChunk * 16;
    }
#pragma unroll
    for (int p = 0; p < 2; p++) {
        int row = warpN * 32 + p * 16 + bRow;
        adrBH[p] = cvta_shared(BsH) + row * 48 + bChunk * 16;
        adrBL[p] = cvta_shared(BsL) + row * 48 + bChunk * 16;
    }

    float acc[MI][NI][4];
#pragma unroll
    for (int mi = 0; mi < MI; mi++)
#pragma unroll
        for (int ni = 0; ni < NI; ni++)
#pragma unroll
            for (int j = 0; j < 4; j++) acc[mi][ni][j] = 0.f;

    uint2 ahr[4], alr[4], bhr[4], blr[4];
    float4 bfr[4];
    auto ldg = [&](int k0) {
#pragma unroll
        for (int i = 0; i < 4; i++) {
            ahr[i] = *reinterpret_cast<const uint2*>(Ah + (size_t)(m0 + am[i]) * lda + k0 + agk[i]);
            if (PASSES == 3)
                alr[i] = *reinterpret_cast<const uint2*>(Al + (size_t)(m0 + am[i]) * lda + k0 + agk[i]);
        }
        if (TRANSB) {
#pragma unroll
            for (int i = 0; i < 4; i++) {
                bhr[i] = *reinterpret_cast<const uint2*>(Bh + (size_t)(n0 + bn[i]) * ldb + k0 + bgk[i]);
                if (PASSES == 3)
                    blr[i] = *reinterpret_cast<const uint2*>(Bl + (size_t)(n0 + bn[i]) * ldb + k0 + bgk[i]);
            }
        } else {
#pragma unroll
            for (int i = 0; i < 4; i++)
                bfr[i] = *reinterpret_cast<const float4*>(Bf + (size_t)(k0 + bgk[i]) * ldb + n0 + bn[i]);
        }
    };
    auto sts = [&](int buf) {
#pragma unroll
        for (int i = 0; i < 4; i++) {
            int o = ((buf * 2 + asub[i]) * BM + am[i]) * LDS + akin[i];
            *reinterpret_cast<uint2*>(&AsH[o]) = ahr[i];
            if (PASSES == 3) *reinterpret_cast<uint2*>(&AsL[o]) = alr[i];
        }
        if (TRANSB) {
#pragma unroll
            for (int i = 0; i < 4; i++) {
                int o = ((buf * 2 + bsub[i]) * BN + bn[i]) * LDS + bkin[i];
                *reinterpret_cast<uint2*>(&BsH[o]) = bhr[i];
                if (PASSES == 3) *reinterpret_cast<uint2*>(&BsL[o]) = blr[i];
            }
        } else {
#pragma unroll
            for (int i = 0; i < 4; i++) {
                bf h0, h1, h2, h3, l0, l1, l2, l3;
                split_bf16(bfr[i].x, h0, l0); split_bf16(bfr[i].y, h1, l1);
                split_bf16(bfr[i].z, h2, l2); split_bf16(bfr[i].w, h3, l3);
                int ob = (buf * 2 + bsub[i]) * BN;
                BsH[(ob + bn[i] + 0) * LDS + bkin[i]] = h0;
                BsH[(ob + bn[i] + 1) * LDS + bkin[i]] = h1;
                BsH[(ob + bn[i] + 2) * LDS + bkin[i]] = h2;
                BsH[(ob + bn[i] + 3) * LDS + bkin[i]] = h3;
                if (PASSES == 3) {
                    BsL[(ob + bn[i] + 0) * LDS + bkin[i]] = l0;
                    BsL[(ob + bn[i] + 1) * LDS + bkin[i]] = l1;
                    BsL[(ob + bn[i] + 2) * LDS + bkin[i]] = l2;
                    BsL[(ob + bn[i] + 3) * LDS + bkin[i]] = l3;
                }
            }
        }
    };

    ldg(0);
    sts(0);
    __syncthreads();

    const int S = K >> 5;
    int buf = 0;
    for (int s = 0; s < S; s++) {
        const bool has_next = (s + 1) < S;
        if (has_next) ldg((s + 1) << 5);

#pragma unroll
        for (int sub = 0; sub < 2; sub++) {
            const uint32_t off = (uint32_t)buf * BUF_B + (uint32_t)sub * SUB_B;
            uint32_t aH[MI][4], aL[MI][4], bH[NI][2], bL[NI][2];
#pragma unroll
            for (int mi = 0; mi < MI; mi++) {
                ldmatrix_x4(aH[mi][0], aH[mi][1], aH[mi][2], aH[mi][3], adrAH[mi] + off);
                if (PASSES == 3)
                    ldmatrix_x4(aL[mi][0], aL[mi][1], aL[mi][2], aL[mi][3], adrAL[mi] + off);
            }
#pragma unroll
            for (int p = 0; p < 2; p++) {
                uint32_t r0, r1, r2, r3;
                ldmatrix_x4(r0, r1, r2, r3, adrBH[p] + off);
                bH[2 * p][0] = r0; bH[2 * p][1] = r1;
                bH[2 * p + 1][0] = r2; bH[2 * p + 1][1] = r3;
                if (PASSES == 3) {
                    ldmatrix_x4(r0, r1, r2, r3, adrBL[p] + off);
                    bL[2 * p][0] = r0; bL[2 * p][1] = r1;
                    bL[2 * p + 1][0] = r2; bL[2 * p + 1][1] = r3;
                }
            }
#pragma unroll
            for (int mi = 0; mi < MI; mi++)
#pragma unroll
                for (int ni = 0; ni < NI; ni++) {
                    mma_bf16(acc[mi][ni], aH[mi][0], aH[mi][1], aH[mi][2], aH[mi][3],
                             bH[ni][0], bH[ni][1]);
                    if (PASSES == 3) {
                        mma_bf16(acc[mi][ni], aH[mi][0], aH[mi][1], aH[mi][2], aH[mi][3],
                                 bL[ni][0], bL[ni][1]);
                        mma_bf16(acc[mi][ni], aL[mi][0], aL[mi][1], aL[mi][2], aL[mi][3],
                                 bH[ni][0], bH[ni][1]);
                    }
                }
        }

        if (has_next) {
            sts(buf ^ 1);
            __syncthreads();
            buf ^= 1;
        }
    }

    const int g = lane >> 2, t = lane & 3;

    if (EPI == 2) {
        __syncthreads();
        uint32_t* smask = reinterpret_cast<uint32_t*>(sm);
        for (int i = tid; i < 512; i += 256) smask[i] = 0u;
        __syncthreads();
#pragma unroll
        for (int mi = 0; mi < MI; mi++)
#pragma unroll
            for (int ni = 0; ni < NI; ni++) {
                int cl = warpN * 32 + ni * 8 + t * 2;
                int rl = warpM * 64 + mi * 16 + g;
                uint32_t b0 = ((alpha * acc[mi][ni][0] > thr) ? 1u : 0u) |
                              ((alpha * acc[mi][ni][1] > thr) ? 2u : 0u);
                uint32_t b1 = ((alpha * acc[mi][ni][2] > thr) ? 1u : 0u) |
                              ((alpha * acc[mi][ni][3] > thr) ? 2u : 0u);
                if (b0) atomicOr(&smask[rl * 4 + (cl >> 5)], b0 << (cl & 31));
                if (b1) atomicOr(&smask[(rl + 8) * 4 + (cl >> 5)], b1 << (cl & 31));
            }
        __syncthreads();
        for (int i = tid; i < 512; i += 256) {
            int r = i >> 2, w = i & 3;
            Cm[(size_t)(m0 + r) * MW_ + (n0 >> 5) + w] = smask[i];
        }
        return;
    }

#pragma unroll
    for (int mi = 0; mi < MI; mi++) {
#pragma unroll
        for (int ni = 0; ni < NI; ni++) {
            int col = n0 + warpN * 32 + ni * 8 + t * 2;
            int r0  = m0 + warpM * 64 + mi * 16 + g;
            float2 o0, o1;
            o0.x = alpha * acc[mi][ni][0];
            o0.y = alpha * acc[mi][ni][1];
            o1.x = alpha * acc[mi][ni][2];
            o1.y = alpha * acc[mi][ni][3];
            if (bias) {
                float2 bv = *reinterpret_cast<const float2*>(bias + col);
                o0.x += bv.x; o0.y += bv.y;
                o1.x += bv.x; o1.y += bv.y;
            }
            if (EPI == 0) {
                *reinterpret_cast<float2*>(Cf + (size_t)r0 * ldc + col)       = o0;
                *reinterpret_cast<float2*>(Cf + (size_t)(r0 + 8) * ldc + col) = o1;
            } else {
                bf h0, l0, h1, l1;
                split_bf16(o0.x, h0, l0); split_bf16(o0.y, h1, l1);
                *reinterpret_cast<__nv_bfloat162*>(Ch + (size_t)r0 * ldc + col) = __nv_bfloat162(h0, h1);
                *reinterpret_cast<__nv_bfloat162*>(Cl + (size_t)r0 * ldc + col) = __nv_bfloat162(l0, l1);
                split_bf16(o1.x, h0, l0); split_bf16(o1.y, h1, l1);
                *reinterpret_cast<__nv_bfloat162*>(Ch + (size_t)(r0 + 8) * ldc + col) = __nv_bfloat162(h0, h1);
                *reinterpret_cast<__nv_bfloat162*>(Cl + (size_t)(r0 + 8) * ldc + col) = __nv_bfloat162(l0, l1);
            }
        }
    }
}

static constexpr int GEMM_SMEM = 16 * 128 * 24 * 2;   // 98304 bytes

template <bool TRANSB, int PASSES, int EPI>
static void run_g(int M, int N, int K,
                  const bf* Ah, const bf* Al, int lda, size_t sA,
                  const bf* Bh, const bf* Bl, const float* Bf, int ldb, size_t sB,
                  float* Cf, bf* Ch, bf* Cl, uint32_t* Cm, float thr,
                  int ldc, size_t sC,
                  float alpha, const float* bias, int batch)
{
    dim3 grid(N / 128, M / 128, batch);
    gemm_tc<TRANSB, PASSES, EPI><<<grid, 256, GEMM_SMEM>>>(
        K, Ah, Al, lda, sA, Bh, Bl, Bf, ldb, sB, Cf, Ch, Cl, Cm, thr, ldc, sC, alpha, bias);
}

// ---------------- reductions ----------------
__device__ __forceinline__ float warpSum(float v) {
#pragma unroll
    for (int o = 16; o; o >>= 1) v += __shfl_xor_sync(0xffffffffu, v, o);
    return v;
}
__device__ __forceinline__ float blockSum(float v, float* red) {
    v = warpSum(v);
    if ((threadIdx.x & 31) == 0) red[threadIdx.x >> 5] = v;
    __syncthreads();
    float r = red[0];
#pragma unroll
    for (int i = 1; i < 8; i++) r += red[i];
    __syncthreads();
    return r;
}

// ---------------- elementwise kernels ----------------
__global__ void split_arr_kernel(const float* __restrict__ s,
                                 bf* __restrict__ h, bf* __restrict__ l, int n)
{
    int t = blockIdx.x * 256 + threadIdx.x;
    if (t < n) {
        bf hh, ll;
        split_bf16(s[t], hh, ll);
        h[t] = hh; l[t] = ll;
    }
}

__global__ void qkv_split_kernel(const float* __restrict__ qkv,
                                 bf* __restrict__ qh, bf* __restrict__ ql,
                                 bf* __restrict__ kh, bf* __restrict__ kl,
                                 float* __restrict__ vf, int coloff,
                                 bf* __restrict__ vnfh,
                                 bf* __restrict__ ehh, bf* __restrict__ ehl,
                                 const float* __restrict__ scores)
{
    int w = (blockIdx.x * blockDim.x + threadIdx.x) >> 5;
    if (w >= N_ * H_) return;
    int lane = threadIdx.x & 31;
    int h = w & 3;
    int n = w >> 2;

    const float* src = qkv + (size_t)n * (3 * C_) + h * D_;
    float q0 = src[lane],            q1 = src[lane + 32];
    float k0 = src[C_ + lane],       k1 = src[C_ + lane + 32];
    float v0 = src[2 * C_ + lane],   v1 = src[2 * C_ + lane + 32];

    float sq = warpSum(q0 * q0 + q1 * q1);
    float sk = warpSum(k0 * k0 + k1 * k1);
    float sv = warpSum(v0 * v0 + v1 * v1);
    float iq = 1.f / fmaxf(sqrtf(sq), 1e-6f);
    float ik = 1.f / fmaxf(sqrtf(sk), 1e-6f);
    float iv = 1.f / fmaxf(sqrtf(sv), 1e-6f);
    float ks = (scores ? 25.f * scores[n] : 25.f) * ik;

    size_t ho = ((size_t)h * N_ + n) * D_;
    bf hh, ll;
    split_bf16(q0 * iq, hh, ll); qh[ho + lane] = hh;      ql[ho + lane] = ll;
    split_bf16(q1 * iq, hh, ll); qh[ho + lane + 32] = hh; ql[ho + lane + 32] = ll;
    split_bf16(k0 * ks, hh, ll); kh[ho + lane] = hh;      kl[ho + lane] = ll;
    split_bf16(k1 * ks, hh, ll); kh[ho + lane + 32] = hh; kl[ho + lane + 32] = ll;

    size_t vo = ((size_t)h * N_ + n) * (2 * D_) + coloff;
    vf[vo + lane] = v0; vf[vo + lane + 32] = v1;

    size_t fo = (size_t)n * C_ + h * D_;
    vnfh[fo + lane]      = __float2bfloat16_rn(v0 * iv);
    vnfh[fo + lane + 32] = __float2bfloat16_rn(v1 * iv);

    size_t eo = (size_t)n * (2 * C_) + C_ + h * D_;
    split_bf16(v0, hh, ll); ehh[eo + lane] = hh;      ehl[eo + lane] = ll;
    split_bf16(v1, hh, ll); ehh[eo + lane + 32] = hh; ehl[eo + lane + 32] = ll;
}

// =======================================================================================
// Fused dual softmax + average, max-free (logits bounded by 25) with hardware __expf.
// attn = 0.5*exp(lc)/sum(exp(lc)) + 0.5*exp(lr)/sum(exp(lr)); writes hi/lo bf16 planes.
// =======================================================================================
__global__ void softmax_avg_kernel(const float* __restrict__ lc_all,
                                   const float* __restrict__ lr_all,
                                   bf* __restrict__ ah, bf* __restrict__ al)
{
    __shared__ float sc[N_];
    __shared__ float sr[N_];
    __shared__ float red[8];
    size_t base = (size_t)blockIdx.x * N_;
    const float* lc = lc_all + base;
    const float* lr = lr_all + base;

    float tc = 0.f, tr = 0.f;
    for (int m = threadIdx.x * 4; m < N_; m += 1024) {
        float4 xc = *reinterpret_cast<const float4*>(lc + m);
        float4 xr = *reinterpret_cast<const float4*>(lr + m);
        float e0 = __expf(xc.x), e1 = __expf(xc.y), e2 = __expf(xc.z), e3 = __expf(xc.w);
        float f0 = __expf(xr.x), f1 = __expf(xr.y), f2 = __expf(xr.z), f3 = __expf(xr.w);
        *reinterpret_cast<float4*>(sc + m) = make_float4(e0, e1, e2, e3);
        *reinterpret_cast<float4*>(sr + m) = make_float4(f0, f1, f2, f3);
        tc += (e0 + e1) + (e2 + e3);
        tr += (f0 + f1) + (f2 + f3);
    }
    tc = blockSum(tc, red);
    tr = blockSum(tr, red);

    float ic = 0.5f / tc, ir = 0.5f / tr;
    for (int m = threadIdx.x * 4; m < N_; m += 1024) {
        float4 ec = *reinterpret_cast<const float4*>(sc + m);
        float4 er = *reinterpret_cast<const float4*>(sr + m);
        bf h0, l0, h1, l1;
        split_bf16(ec.x * ic + er.x * ir, h0, l0);
        split_bf16(ec.y * ic + er.y * ir, h1, l1);
        *reinterpret_cast<__nv_bfloat162*>(ah + base + m)     = __nv_bfloat162(h0, h1);
        *reinterpret_cast<__nv_bfloat162*>(al + base + m)     = __nv_bfloat162(l0, l1);
        split_bf16(ec.z * ic + er.z * ir, h0, l0);
        split_bf16(ec.w * ic + er.w * ir, h1, l1);
        *reinterpret_cast<__nv_bfloat162*>(ah + base + m + 2) = __nv_bfloat162(h0, h1);
        *reinterpret_cast<__nv_bfloat162*>(al + base + m + 2) = __nv_bfloat162(l0, l1);
    }
}

// =======================================================================================
// Sparse sim: one warp per row; bitmask scan (ascending, deterministic); softmax max &
// denominator cancel exactly under the cls mask.
// =======================================================================================
__global__ __launch_bounds__(256)
void sim_sparse_kernel(const bf* __restrict__ ah, const bf* __restrict__ al,
                       const uint32_t* __restrict__ maskC,
                       const uint32_t* __restrict__ maskR,
                       int*  __restrict__ s_idx, float* __restrict__ s_val,
                       int*  __restrict__ s_cnt,
                       int*  __restrict__ o_idx, float* __restrict__ o_val,
                       int*  __restrict__ o_cnt)
{
    int warp = (blockIdx.x * 256 + threadIdx.x) >> 5;
    if (warp >= N_) return;
    int lane = threadIdx.x & 31;
    int n = warp;
    size_t ro = (size_t)n * N_;
    const uint32_t* mc = maskC + (size_t)n * MW_;
    const uint32_t* mr = maskR + (size_t)n * MW_;
    unsigned ltm = (lane == 0) ? 0u : (0xffffffffu >> (32 - lane));

    int cnt = 0;
    float sumE = 0.f;
#pragma unroll
    for (int c = 0; c < 3; c++) {
        uint32_t w = mc[c * 32 + lane];
        int nb = __popc(w);
        int x = nb;
#pragma unroll
        for (int o = 1; o < 32; o <<= 1) {
            int y = __shfl_up_sync(0xffffffffu, x, o);
            if (lane >= o) x += y;
        }
        int off = x - nb;
        int tot = __shfl_sync(0xffffffffu, x, 31);
        uint32_t ww = w;
        int j = 0;
        while (ww) {
            int b = __ffs(ww) - 1;
            ww &= ww - 1;
            int m = (c * 32 + lane) * 32 + b;
            float s = 0.f;
#pragma unroll
            for (int h = 0; h < 4; h++) {
                size_t o2 = (size_t)h * HS_ + ro + m;
                s += __bfloat162float(ah[o2]) + __bfloat162float(al[o2]);
            }
            s *= 0.25f;
            float e = __expf(s);
            s_idx[ro + cnt + off + j] = m;
            s_val[ro + cnt + off + j] = e;
            sumE += e;
            j++;
        }
        cnt += tot;
    }
    sumE = warpSum(sumE);
    float inv = 1.f / sumE;
    __syncwarp();

    float s2 = 0.f;
    for (int i = lane; i < cnt; i += 32) {
        float v = s_val[ro + i] * inv;
        s_val[ro + i] = v;
        s2 += v;
    }
    s2 = warpSum(s2);
    float inv2 = 1.f / s2;
    __syncwarp();

    int oc = 0;
    for (int i0 = 0; i0 < cnt; i0 += 32) {
        int i = i0 + lane;
        bool keep = false;
        int m = 0; float v = 0.f;
        if (i < cnt) {
            m = s_idx[ro + i];
            v = s_val[ro + i];
            keep = (mr[m >> 5] >> (m & 31)) & 1u;
        }
        unsigned bal = __ballot_sync(0xffffffffu, keep);
        if (keep) {
            int p = oc + __popc(bal & ltm);
            o_idx[ro + p] = m;
            o_val[ro + p] = v * inv2;
        }
        oc += __popc(bal);
    }
    if (lane == 0) { s_cnt[n] = cnt; o_cnt[n] = oc; }
}

// sparse pooled mix on bf16 hi/lo pool planes (reads cols 512:1024, writes 0:512)
__global__ __launch_bounds__(128)
void pool_kernel(const int* __restrict__ idx, const float* __restrict__ val,
                 const int* __restrict__ cnt,
                 bf* __restrict__ ph, bf* __restrict__ pl)
{
    int n = blockIdx.x;
    int k = cnt[n];
    size_t ro = (size_t)n * N_;
    int c = threadIdx.x * 4;

    float acc[4] = {0.f, 0.f, 0.f, 0.f};
    for (int j = 0; j < k; j++) {
        int   m = idx[ro + j];
        float w = val[ro + j];
        size_t o = (size_t)m * 1024 + 512 + c;
        __nv_bfloat162 h0 = *reinterpret_cast<const __nv_bfloat162*>(ph + o);
        __nv_bfloat162 h1 = *reinterpret_cast<const __nv_bfloat162*>(ph + o + 2);
        __nv_bfloat162 l0 = *reinterpret_cast<const __nv_bfloat162*>(pl + o);
        __nv_bfloat162 l1 = *reinterpret_cast<const __nv_bfloat162*>(pl + o + 2);
        acc[0] += w * (__bfloat162float(h0.x) + __bfloat162float(l0.x));
        acc[1] += w * (__bfloat162float(h0.y) + __bfloat162float(l0.y));
        acc[2] += w * (__bfloat162float(h1.x) + __bfloat162float(l1.x));
        acc[3] += w * (__bfloat162float(h1.y) + __bfloat162float(l1.y));
    }
    size_t o = (size_t)n * 1024 + c;
    bf h0, l0, h1, l1;
    split_bf16(acc[0], h0, l0); split_bf16(acc[1], h1, l1);
    *reinterpret_cast<__nv_bfloat162*>(ph + o)     = __nv_bfloat162(h0, h1);
    *reinterpret_cast<__nv_bfloat162*>(pl + o)     = __nv_bfloat162(l0, l1);
    split_bf16(acc[2], h0, l0); split_bf16(acc[3], h1, l1);
    *reinterpret_cast<__nv_bfloat162*>(ph + o + 2) = __nv_bfloat162(h0, h1);
    *reinterpret_cast<__nv_bfloat162*>(pl + o + 2) = __nv_bfloat162(l0, l1);
}

// scatter av f32 [h][n][128] into enh inter halves (hi/lo planes)
__global__ __launch_bounds__(256)
void scatter_av_kernel(const float* __restrict__ av,
                       bf* __restrict__ ech, bf* __restrict__ ecl,
                       bf* __restrict__ erh, bf* __restrict__ erl)
{
    int t = blockIdx.x * 256 + threadIdx.x;
    int h   = t / (N_ * 32);
    int rem = t - h * (N_ * 32);
    int n   = rem >> 5;
    int q   = rem & 31;
    float4 v = *reinterpret_cast<const float4*>(av + ((size_t)h * N_ + n) * 128 + q * 4);
    bf* dh; bf* dl; int col;
    if (q < 16) { dh = ech; dl = ecl; col = h * 64 + q * 4; }
    else        { dh = erh; dl = erl; col = h * 64 + (q - 16) * 4; }
    size_t o = (size_t)n * 512 + col;
    bf h0, l0, h1, l1;
    split_bf16(v.x, h0, l0); split_bf16(v.y, h1, l1);
    *reinterpret_cast<__nv_bfloat162*>(dh + o)     = __nv_bfloat162(h0, h1);
    *reinterpret_cast<__nv_bfloat162*>(dl + o)     = __nv_bfloat162(l0, l1);
    split_bf16(v.z, h0, l0); split_bf16(v.w, h1, l1);
    *reinterpret_cast<__nv_bfloat162*>(dh + o + 2) = __nv_bfloat162(h0, h1);
    *reinterpret_cast<__nv_bfloat162*>(dl + o + 2) = __nv_bfloat162(l0, l1);
}

static void split_arr(const float* s, bf* h, bf* l, int n)
{
    split_arr_kernel<<<(n + 255) / 256, 256>>>(s, h, l, n);
}
template <typename T>
static T* sym(const void* s) { void* p; cudaGetSymbolAddress(&p, s); return (T*)p; }

extern "C" void kernel_launch(void* const* d_in, const int* in_sizes, int n_in,
                              void* d_out, int out_size)
{
    (void)in_sizes; (void)n_in; (void)out_size;

    cudaFuncSetAttribute(gemm_tc<true, 3, 0>,  cudaFuncAttributeMaxDynamicSharedMemorySize, GEMM_SMEM);
    cudaFuncSetAttribute(gemm_tc<true, 3, 1>,  cudaFuncAttributeMaxDynamicSharedMemorySize, GEMM_SMEM);
    cudaFuncSetAttribute(gemm_tc<true, 1, 2>,  cudaFuncAttributeMaxDynamicSharedMemorySize, GEMM_SMEM);
    cudaFuncSetAttribute(gemm_tc<false, 3, 0>, cudaFuncAttributeMaxDynamicSharedMemorySize, GEMM_SMEM);

    const float* cls_features = (const float*)d_in[0];
    const float* reg_features = (const float*)d_in[1];
    const float* cls_scores   = (const float*)d_in[2];
    const float* reg_proj_w   = (const float*)d_in[3];
    const float* qkv_cls_w    = (const float*)d_in[4];
    const float* qkv_reg_w    = (const float*)d_in[5];
    const float* l1_cls_w     = (const float*)d_in[6];
    const float* l1_cls_b     = (const float*)d_in[7];
    const float* l1_reg_w     = (const float*)d_in[8];
    const float* l1_reg_b     = (const float*)d_in[9];
    const float* l2_cls_w     = (const float*)d_in[10];
    const float* l2_cls_b     = (const float*)d_in[11];
    const float* l2_reg_w     = (const float*)d_in[12];
    const float* l2_reg_b     = (const float*)d_in[13];
    float* out = (float*)d_out;

    bf *fCh = sym<bf>(g_featC_h), *fCl = sym<bf>(g_featC_l);
    bf *fRh = sym<bf>(g_featR_h), *fRl = sym<bf>(g_featR_l);
    bf *pWh = sym<bf>(g_projW_h), *pWl = sym<bf>(g_projW_l);
    bf *qcWh = sym<bf>(g_qkvcW_h), *qcWl = sym<bf>(g_qkvcW_l);
    bf *qrWh = sym<bf>(g_qkvrW_h), *qrWl = sym<bf>(g_qkvrW_l);
    bf *l1cWh = sym<bf>(g_l1cW_h), *l1cWl = sym<bf>(g_l1cW_l);
    bf *l1rWh = sym<bf>(g_l1rW_h), *l1rWl = sym<bf>(g_l1rW_l);
    bf *l2cWh = sym<bf>(g_l2cW_h), *l2cWl = sym<bf>(g_l2cW_l);
    bf *l2rWh = sym<bf>(g_l2rW_h), *l2rWl = sym<bf>(g_l2rW_l);
    bf *rph = sym<bf>(g_regp_h),  *rpl = sym<bf>(g_regp_l);
    bf *qch = sym<bf>(g_qnc_h), *qcl = sym<bf>(g_qnc_l);
    bf *kch = sym<bf>(g_knc_h), *kcl = sym<bf>(g_knc_l);
    bf *qrh = sym<bf>(g_qnr_h), *qrl = sym<bf>(g_qnr_l);
    bf *krh = sym<bf>(g_knr_h), *krl = sym<bf>(g_knr_l);
    bf *vnfc = sym<bf>(g_vnfc_h), *vnfr = sym<bf>(g_vnfr_h);
    bf *ath = sym<bf>(g_attn_h), *atl = sym<bf>(g_attn_l);
    bf *ech = sym<bf>(g_enhc_h), *ecl = sym<bf>(g_enhc_l);
    bf *erh = sym<bf>(g_enhr_h), *erl = sym<bf>(g_enhr_l);
    bf *pch = sym<bf>(g_poolc_h), *pcl = sym<bf>(g_poolc_l);
    bf *prh = sym<bf>(g_poolr_h), *prl = sym<bf>(g_poolr_l);
    float *qkvc = sym<float>(g_qkv_cls), *qkvr = sym<float>(g_qkv_reg);
    float *vf = sym<float>(g_vfused), *av = sym<float>(g_av);
    float *bufA = sym<float>(g_bufA), *bufB = sym<float>(g_bufB);
    uint32_t *mC = sym<uint32_t>(g_maskC), *mR = sym<uint32_t>(g_maskR);
    float *sr2v = sym<float>(g_sr2v), *objv = sym<float>(g_objv);
    int *sr2i = sym<int>(g_sr2i), *sr2c = sym<int>(g_sr2c);
    int *obji = sym<int>(g_obji), *objc = sym<int>(g_objc);

    // 0) pre-split inputs & weights into hi/lo bf16 planes
    split_arr(cls_features, fCh, fCl, N_ * C_);
    split_arr(reg_features, fRh, fRl, N_ * D_);
    split_arr(reg_proj_w,   pWh, pWl, C_ * D_);
    split_arr(qkv_cls_w,    qcWh, qcWl, 3 * C_ * C_);
    split_arr(qkv_reg_w,    qrWh, qrWl, 3 * C_ * C_);
    split_arr(l1_cls_w,     l1cWh, l1cWl, 4 * C_ * C_);
    split_arr(l1_reg_w,     l1rWh, l1rWl, 4 * C_ * C_);
    split_arr(l2_cls_w,     l2cWh, l2cWl, 16 * C_ * C_);
    split_arr(l2_reg_w,     l2rWh, l2rWl, 16 * C_ * C_);

    // 1) reg branch 1x1 projection -> regp planes
    run_g<true, 3, 1>(N_, C_, D_, fRh, fRl, D_, 0, pWh, pWl, nullptr, D_, 0,
                      nullptr, rph, rpl, nullptr, 0.f, C_, 0, 1.f, nullptr, 1);

    // 2) QKV projections -> f32
    run_g<true, 3, 0>(N_, 3 * C_, C_, fCh, fCl, C_, 0, qcWh, qcWl, nullptr, C_, 0,
                      qkvc, nullptr, nullptr, nullptr, 0.f, 3 * C_, 0, 1.f, nullptr, 1);
    run_g<true, 3, 0>(N_, 3 * C_, C_, rph, rpl, C_, 0, qrWh, qrWl, nullptr, C_, 0,
                      qkvr, nullptr, nullptr, nullptr, 0.f, 3 * C_, 0, 1.f, nullptr, 1);

    // 3) split + normalize (scale baked into k planes)
    qkv_split_kernel<<<(N_ * H_ * 32 + 255) / 256, 256>>>(
        qkvc, qch, qcl, kch, kcl, vf, 0,  vnfc, ech, ecl, cls_scores);
    qkv_split_kernel<<<(N_ * H_ * 32 + 255) / 256, 256>>>(
        qkvr, qrh, qrl, krh, krl, vf, 64, vnfr, erh, erl, nullptr);

    // 4) attention logits per head (pre-scaled) -> f32
    run_g<true, 3, 0>(N_, N_, D_, qch, qcl, D_, QS_, kch, kcl, nullptr, D_, QS_,
                      bufA, nullptr, nullptr, nullptr, 0.f, N_, HS_, 1.f, nullptr, H_);
    run_g<true, 3, 0>(N_, N_, D_, qrh, qrl, D_, QS_, krh, krl, nullptr, D_, QS_,
                      bufB, nullptr, nullptr, nullptr, 0.f, N_, HS_, 1.f, nullptr, H_);

    // 5) fused dual softmax + average (max-free, __expf) -> attn planes
    softmax_avg_kernel<<<H_ * N_, 256>>>(bufA, bufB, ath, atl);

    // 6) gram matrices, 1-pass bf16 -> threshold BITMASKS
    run_g<true, 1, 2>(N_, N_, C_, vnfc, vnfc, C_, 0, vnfc, vnfc, nullptr, C_, 0,
                      nullptr, nullptr, nullptr, mC, 0.75f, N_, 0, 0.25f, nullptr, 1);
    run_g<true, 1, 2>(N_, N_, C_, vnfr, vnfr, C_, 0, vnfr, vnfr, nullptr, C_, 0,
                      nullptr, nullptr, nullptr, mR, 0.99f, N_, 0, 0.25f, nullptr, 1);

    // 7) sparse sim -> CSR lists
    sim_sparse_kernel<<<(N_ * 32 + 255) / 256, 256>>>(
        ath, atl, mC, mR, sr2i, sr2v, sr2c, obji, objv, objc);

    // 8) attn @ [v_cls|v_reg] per head -> av, scatter into enh halves
    run_g<false, 3, 0>(N_, 128, N_, ath, atl, N_, HS_,
                       nullptr, nullptr, vf, 128, (size_t)N_ * 128,
                       av, nullptr, nullptr, nullptr, 0.f, 128, (size_t)N_ * 128,
                       1.f, nullptr, H_);
    scatter_av_kernel<<<(H_ * N_ * 32) / 256, 256>>>(av, ech, ecl, erh, erl);

    // 9) l1 linears -> pool planes cols [512,1024)
    run_g<true, 3, 1>(N_, 2 * C_, 2 * C_, ech, ecl, 2 * C_, 0, l1cWh, l1cWl, nullptr, 2 * C_, 0,
                      nullptr, pch + 2 * C_, pcl + 2 * C_, nullptr, 0.f, 4 * C_, 0, 1.f, l1_cls_b, 1);
    run_g<true, 3, 1>(N_, 2 * C_, 2 * C_, erh, erl, 2 * C_, 0, l1rWh, l1rWl, nullptr, 2 * C_, 0,
                      nullptr, prh + 2 * C_, prl + 2 * C_, nullptr, 0.f, 4 * C_, 0, 1.f, l1_reg_b, 1);

    // 10) pooled inter via sparse gather -> pool planes cols [0,512)
    pool_kernel<<<N_, 128>>>(sr2i, sr2v, sr2c, pch, pcl);
    pool_kernel<<<N_, 128>>>(obji, objv, objc, prh, prl);

    // 11) l2 linears -> f32 outputs
    run_g<true, 3, 0>(N_, 4 * C_, 4 * C_, pch, pcl, 4 * C_, 0, l2cWh, l2cWl, nullptr, 4 * C_, 0,
                      out, nullptr, nullptr, nullptr, 0.f, 4 * C_, 0, 1.f, l2_cls_b, 1);
    run_g<true, 3, 0>(N_, 4 * C_, 4 * C_, prh, prl, 4 * C_, 0, l2rWh, l2rWl, nullptr, 4 * C_, 0,
                      out + (size_t)N_ * 4 * C_, nullptr, nullptr, nullptr, 0.f, 4 * C_, 0,
                      1.f, l2_reg_b, 1);
}